// round 1
// baseline (speedup 1.0000x reference)
#include <cuda_runtime.h>
#include <cuda_bf16.h>
#include <math.h>

// ---------------------------------------------------------------------------
// CAT_Attention  (B=1, BLOCK=2048, CHUNK=64, DIM=1024, CAT=1024, NH=16, HD=64)
// S = 2081, W = 65, NC = 32
// ---------------------------------------------------------------------------

#define S_LEN   2081
#define CATD    1024
#define NHEAD   16
#define HEADD   64
#define NCHUNK  32
#define WWIN    65
#define KSLICES 128   // split-K slices for comp GEMM (each 512 k)

// -------------------- scratch (device globals; no allocs) -------------------
__device__ float g_fxpart[KSLICES * 32 * 1024];   // 16 MB  partials of comp GEMM
__device__ float g_h   [S_LEN * CATD];            // 8.5 MB  assembled sequence
__device__ float g_qkv [S_LEN * 3 * CATD];        // 25.6 MB q|k|v
__device__ float g_y   [S_LEN * CATD];            // attn out
__device__ float g_y2  [S_LEN * CATD];            // y @ W_o

// -------------------- row maps ---------------------------------------------
__device__ __forceinline__ int amap_final(int r) {
    // out row r -> y2 row
    if (r < 63)    return r + 1;           // yk[0, 1:64]
    if (r == 2047) return 2080;            // y_last
    int u = r - 63;                        // c = 1 + u/64, t = u%64 -> c*65+t
    return 65 + u + (u >> 6);
}

// ---------------------------------------------------------------------------
// Generic FP32 SGEMM, 128x128x8 tile, 256 threads, 8x8 per thread.
// AMODE: 0 = identity A rows, 1 = gather (final output selection)
// CMODE: 0 = identity C rows, 1 = scatter into h (expand: r -> (r/64)*65+1+r%64)
// ---------------------------------------------------------------------------
template<int AMODE, int CMODE>
__global__ __launch_bounds__(256)
void sgemm_kernel(const float* __restrict__ A, const float* __restrict__ B,
                  float* __restrict__ C, int M, int N, int K)
{
    __shared__ float As[8][128];
    __shared__ float Bs[8][128];

    const int tid = threadIdx.x;
    const int bn = blockIdx.x * 128;
    const int bm = blockIdx.y * 128;
    const int tx = tid & 15;
    const int ty = tid >> 4;

    // global-load assignments
    const int ar = tid >> 1;                 // 0..127 (A tile row)
    const int ac = (tid & 1) * 4;            // 0 or 4 (A tile col group)
    const int br = tid >> 5;                 // 0..7  (B tile row)
    const int bc = (tid & 31) * 4;           // 0..124 (B tile col)

    const int agr = bm + ar;
    const bool aval = (agr < M);
    int arow = 0;
    if (aval) arow = (AMODE == 1) ? amap_final(agr) : agr;
    const float* Aptr = A + (size_t)arow * K + ac;
    const float* Bptr = B + (size_t)br * N + bn + bc;

    float acc[8][8];
#pragma unroll
    for (int i = 0; i < 8; i++)
#pragma unroll
        for (int j = 0; j < 8; j++) acc[i][j] = 0.f;

    for (int k0 = 0; k0 < K; k0 += 8) {
        float4 av = make_float4(0.f, 0.f, 0.f, 0.f);
        if (aval) av = *(const float4*)(Aptr + k0);
        float4 bv = *(const float4*)(Bptr + (size_t)k0 * N);

        __syncthreads();   // previous compute done before overwriting smem
        As[ac + 0][ar] = av.x;
        As[ac + 1][ar] = av.y;
        As[ac + 2][ar] = av.z;
        As[ac + 3][ar] = av.w;
        *(float4*)&Bs[br][bc] = bv;
        __syncthreads();

#pragma unroll
        for (int kk = 0; kk < 8; kk++) {
            float a[8], b[8];
            *(float4*)&a[0] = *(const float4*)&As[kk][ty * 8];
            *(float4*)&a[4] = *(const float4*)&As[kk][ty * 8 + 4];
            *(float4*)&b[0] = *(const float4*)&Bs[kk][tx * 8];
            *(float4*)&b[4] = *(const float4*)&Bs[kk][tx * 8 + 4];
#pragma unroll
            for (int i = 0; i < 8; i++)
#pragma unroll
                for (int j = 0; j < 8; j++)
                    acc[i][j] += a[i] * b[j];
        }
    }

#pragma unroll
    for (int i = 0; i < 8; i++) {
        int gr = bm + ty * 8 + i;
        if (gr >= M) continue;
        int cr = (CMODE == 1) ? ((gr >> 6) * 65 + 1 + (gr & 63)) : gr;
        float4 o1 = make_float4(acc[i][0], acc[i][1], acc[i][2], acc[i][3]);
        float4 o2 = make_float4(acc[i][4], acc[i][5], acc[i][6], acc[i][7]);
        *(float4*)&C[(size_t)cr * N + bn + tx * 8]     = o1;
        *(float4*)&C[(size_t)cr * N + bn + tx * 8 + 4] = o2;
    }
}

// ---------------------------------------------------------------------------
// comp GEMM: fx[m] = x.reshape(32, 65536) @ W_comp  -> deterministic split-K.
// grid (KSLICES, 2); block 256. Each thread owns 2 output columns, 32 rows.
// ---------------------------------------------------------------------------
__global__ __launch_bounds__(256)
void comp_kernel(const float* __restrict__ x, const float* __restrict__ Wc,
                 float* __restrict__ fxpart)
{
    __shared__ float As[32][33];
    const int tid = threadIdx.x;
    const int n = blockIdx.y * 512 + tid * 2;
    const int kbase = blockIdx.x * 512;
    const int slice = blockIdx.x;

    float2 acc[32];
#pragma unroll
    for (int m = 0; m < 32; m++) acc[m] = make_float2(0.f, 0.f);

    for (int k0 = kbase; k0 < kbase + 512; k0 += 32) {
        __syncthreads();
#pragma unroll
        for (int s = 0; s < 4; s++) {
            int i = s * 256 + tid;
            int m = i >> 5, kc = i & 31;
            As[m][kc] = x[m * 65536 + k0 + kc];
        }
        __syncthreads();
#pragma unroll 8
        for (int kc = 0; kc < 32; kc++) {
            float2 w = *(const float2*)&Wc[(size_t)(k0 + kc) * 1024 + n];
#pragma unroll
            for (int m = 0; m < 32; m++) {
                float a = As[m][kc];
                acc[m].x += a * w.x;
                acc[m].y += a * w.y;
            }
        }
    }
#pragma unroll
    for (int m = 0; m < 32; m++) {
        float* dst = &fxpart[(size_t)(slice * 32 + m) * 1024 + n];
        dst[0] = acc[m].x;
        dst[1] = acc[m].y;
    }
}

// reduce split-K partials, add bias / dummy, write anchor rows of h
__global__ void fx_finalize(const float* __restrict__ fxpart,
                            const float* __restrict__ dummy,
                            const float* __restrict__ bias,
                            float* __restrict__ h)
{
    int c = blockIdx.x;          // 0..32 (FX row)
    int n = threadIdx.x;         // 0..1023
    float v;
    if (c == 0) {
        v = dummy[n];
    } else {
        int m = c - 1;
        float s = bias[n];
        for (int sl = 0; sl < KSLICES; sl++)
            s += fxpart[(size_t)(sl * 32 + m) * 1024 + n];
        v = s;
    }
    int hrow = (c < 32) ? c * 65 : 2080;
    h[(size_t)hrow * CATD + n] = v;
}

// ---------------------------------------------------------------------------
// RoPE (in-place on q,k sections of g_qkv). One thread per (pos, head, pair).
// ---------------------------------------------------------------------------
__global__ void rope_kernel(float* __restrict__ qkv,
                            const float* __restrict__ cosb,
                            const float* __restrict__ sinb)
{
    int gid = blockIdx.x * blockDim.x + threadIdx.x;
    if (gid >= S_LEN * NHEAD * 32) return;
    int i = gid & 31;
    int head = (gid >> 5) & 15;
    int pos = gid >> 9;
    float c0 = cosb[pos * 64 + i],      s0 = sinb[pos * 64 + i];
    float c1 = cosb[pos * 64 + i + 32], s1 = sinb[pos * 64 + i + 32];
    size_t base = (size_t)pos * 3072 + head * 64;
#pragma unroll
    for (int part = 0; part < 2; part++) {
        float* p = qkv + base + part * 1024;
        float a = p[i], b = p[i + 32];
        p[i]      = a * c0 - b * s0;
        p[i + 32] = b * c1 + a * s1;
    }
}

// ---------------------------------------------------------------------------
// Sparse CAT attention. grid (33 chunks, 16 heads); block 256 (8 warps).
// Query p = cq*65+j attends to anchors {0,65,..,(cq-1)*65} + chunk [cq*65, p].
// One warp per query; lanes parallel over HD (2 dims each).
// ---------------------------------------------------------------------------
__global__ __launch_bounds__(256)
void attn_kernel(const float* __restrict__ qkv, float* __restrict__ y)
{
    __shared__ float sprob[8][104];
    const int cq = blockIdx.x;
    const int head = blockIdx.y;
    const int warp = threadIdx.x >> 5;
    const int lane = threadIdx.x & 31;
    const int cnt = (cq == 32) ? 1 : 65;

    for (int j = warp; j < cnt; j += 8) {
        const int p = cq * 65 + j;
        float2 q2 = *(const float2*)(qkv + (size_t)p * 3072 + head * 64 + 2 * lane);
        const int nkeys = cq + j + 1;

        float mx = -1e30f;
        for (int kk = 0; kk < nkeys; kk++) {
            int kp = (kk < cq) ? kk * 65 : cq * 65 + (kk - cq);
            float2 k2 = *(const float2*)(qkv + (size_t)kp * 3072 + 1024 + head * 64 + 2 * lane);
            float s = q2.x * k2.x + q2.y * k2.y;
            s += __shfl_xor_sync(0xffffffffu, s, 16);
            s += __shfl_xor_sync(0xffffffffu, s, 8);
            s += __shfl_xor_sync(0xffffffffu, s, 4);
            s += __shfl_xor_sync(0xffffffffu, s, 2);
            s += __shfl_xor_sync(0xffffffffu, s, 1);
            s *= 0.125f;                    // 1/sqrt(64)
            if (lane == 0) sprob[warp][kk] = s;
            mx = fmaxf(mx, s);              // s identical on all lanes
        }
        __syncwarp();

        float sum = 0.f;
        for (int kk = lane; kk < nkeys; kk += 32) {
            float e = __expf(sprob[warp][kk] - mx);
            sprob[warp][kk] = e;
            sum += e;
        }
        sum += __shfl_xor_sync(0xffffffffu, sum, 16);
        sum += __shfl_xor_sync(0xffffffffu, sum, 8);
        sum += __shfl_xor_sync(0xffffffffu, sum, 4);
        sum += __shfl_xor_sync(0xffffffffu, sum, 2);
        sum += __shfl_xor_sync(0xffffffffu, sum, 1);
        __syncwarp();
        float inv = 1.f / sum;

        float2 acc = make_float2(0.f, 0.f);
        for (int kk = 0; kk < nkeys; kk++) {
            int kp = (kk < cq) ? kk * 65 : cq * 65 + (kk - cq);
            float pr = sprob[warp][kk];
            float2 v2 = *(const float2*)(qkv + (size_t)kp * 3072 + 2048 + head * 64 + 2 * lane);
            acc.x += pr * v2.x;
            acc.y += pr * v2.y;
        }
        float2 o = make_float2(acc.x * inv, acc.y * inv);
        *(float2*)(y + (size_t)p * 1024 + head * 64 + 2 * lane) = o;
        __syncwarp();
    }
}

// ---------------------------------------------------------------------------
extern "C" void kernel_launch(void* const* d_in, const int* in_sizes, int n_in,
                              void* d_out, int out_size)
{
    const float* x        = (const float*)d_in[0];
    const float* W_expand = (const float*)d_in[1];
    const float* W_comp   = (const float*)d_in[2];
    const float* b_comp   = (const float*)d_in[3];
    const float* dummy_fx = (const float*)d_in[4];
    const float* W_qkv    = (const float*)d_in[5];
    const float* W_o      = (const float*)d_in[6];
    const float* W_final  = (const float*)d_in[7];
    const float* cosb     = (const float*)d_in[8];
    const float* sinb     = (const float*)d_in[9];
    float* out = (float*)d_out;

    float *fxpart, *h, *qkv, *y, *y2;
    cudaGetSymbolAddress((void**)&fxpart, g_fxpart);
    cudaGetSymbolAddress((void**)&h,      g_h);
    cudaGetSymbolAddress((void**)&qkv,    g_qkv);
    cudaGetSymbolAddress((void**)&y,      g_y);
    cudaGetSymbolAddress((void**)&y2,     g_y2);

    // 1. fx = x.reshape(32,65536) @ W_comp   (split-K, deterministic)
    comp_kernel<<<dim3(KSLICES, 2), 256>>>(x, W_comp, fxpart);

    // 2. reduce partials (+bias, dummy) -> anchor rows of h
    fx_finalize<<<33, 1024>>>(fxpart, dummy_fx, b_comp, h);

    // 3. xe = x @ W_expand, scattered into non-anchor rows of h
    sgemm_kernel<0, 1><<<dim3(8, 16), 256>>>(x, W_expand, h, 2048, 1024, 1024);

    // 4. qkv = h @ W_qkv
    sgemm_kernel<0, 0><<<dim3(24, 17), 256>>>(h, W_qkv, qkv, S_LEN, 3072, 1024);

    // 5. RoPE on q and k
    rope_kernel<<<(S_LEN * NHEAD * 32 + 255) / 256, 256>>>(qkv, cosb, sinb);

    // 6. sparse CAT attention
    attn_kernel<<<dim3(33, 16), 256>>>(qkv, y);

    // 7. y2 = y @ W_o
    sgemm_kernel<0, 0><<<dim3(8, 17), 256>>>(y, W_o, y2, S_LEN, 1024, 1024);

    // 8. out = gather(y2) @ W_final
    sgemm_kernel<1, 0><<<dim3(8, 16), 256>>>(y2, W_final, out, 2048, 1024, 1024);
}

// round 2
// speedup vs baseline: 1.8790x; 1.8790x over previous
#include <cuda_runtime.h>
#include <cuda_bf16.h>
#include <math.h>
#include <stdint.h>

// ---------------------------------------------------------------------------
// CAT_Attention  (B=1, BLOCK=2048, CHUNK=64, DIM=1024, CAT=1024, NH=16, HD=64)
// S = 2081, W = 65, NC = 32
// Round 2: dense GEMMs on tensor cores (bf16 mma.sync, 2-term hi/lo split).
// ---------------------------------------------------------------------------

#define S_LEN   2081
#define CATD    1024
#define NHEAD   16
#define NCHUNK  32
#define KSLICES 128

// -------------------- scratch (device globals; no allocs) -------------------
__device__ float g_fxpart[KSLICES * 32 * 1024];
__device__ float g_h   [S_LEN * CATD];
__device__ float g_qkv [S_LEN * 3 * CATD];
__device__ float g_y   [S_LEN * CATD];
__device__ float g_y2  [S_LEN * CATD];

// -------------------- row maps ---------------------------------------------
__device__ __forceinline__ int amap_final(int r) {
    if (r < 63)    return r + 1;
    if (r == 2047) return 2080;
    int u = r - 63;
    return 65 + u + (u >> 6);
}

// -------------------- helpers ----------------------------------------------
__device__ __forceinline__ uint32_t smem_u32(const void* p) {
    return (uint32_t)__cvta_generic_to_shared(p);
}

__device__ __forceinline__ uint32_t pack_bf2(__nv_bfloat16 a, __nv_bfloat16 b) {
    __nv_bfloat162 t = __halves2bfloat162(a, b);
    return *(uint32_t*)&t;
}

__device__ __forceinline__ void mma16816(float* c, const uint32_t* a, const uint32_t* b) {
    asm volatile(
        "mma.sync.aligned.m16n8k16.row.col.f32.bf16.bf16.f32 "
        "{%0,%1,%2,%3}, {%4,%5,%6,%7}, {%8,%9}, {%0,%1,%2,%3};"
        : "+f"(c[0]), "+f"(c[1]), "+f"(c[2]), "+f"(c[3])
        : "r"(a[0]), "r"(a[1]), "r"(a[2]), "r"(a[3]), "r"(b[0]), "r"(b[1]));
}

__device__ __forceinline__ void ldmat4t(uint32_t* r, uint32_t addr) {
    asm volatile(
        "ldmatrix.sync.aligned.m8n8.x4.trans.shared.b16 {%0,%1,%2,%3}, [%4];"
        : "=r"(r[0]), "=r"(r[1]), "=r"(r[2]), "=r"(r[3]) : "r"(addr));
}

// ---------------------------------------------------------------------------
// Tensor-core GEMM: C[M,N] = A[M,K] @ B[K,N], fp32 in/out, bf16 hi/lo split.
// Tile 128x128x32, 256 threads (8 warps, 4x2), warp tile 32x64.
// AMODE: 1 = gather A rows via amap_final. CMODE: 1 = scatter C rows into h.
// Requires: K % 32 == 0, N % 128 == 0.
// ---------------------------------------------------------------------------
template<int AMODE, int CMODE>
__global__ __launch_bounds__(256, 2)
void mma_gemm(const float* __restrict__ A, const float* __restrict__ B,
              float* __restrict__ C, int M, int N, int K)
{
    __shared__ __nv_bfloat16 Ahi[128][40];
    __shared__ __nv_bfloat16 Alo[128][40];
    __shared__ __nv_bfloat16 Bhi[32][136];
    __shared__ __nv_bfloat16 Blo[32][136];

    const int tid = threadIdx.x;
    const int wid = tid >> 5, lane = tid & 31;
    const int warp_m = wid & 3, warp_n = wid >> 2;
    const int bm = blockIdx.y * 128;
    const int bn = blockIdx.x * 128;

    float acc[16][4];
#pragma unroll
    for (int i = 0; i < 16; i++)
#pragma unroll
        for (int j = 0; j < 4; j++) acc[i][j] = 0.f;

    // global A-row assignment (4 rows per thread)
    int  arow_g[4];
    bool aval[4];
#pragma unroll
    for (int i = 0; i < 4; i++) {
        int e = tid + i * 256;
        int gr = bm + (e >> 3);
        aval[i] = (gr < M);
        int r = aval[i] ? gr : 0;
        arow_g[i] = (AMODE == 1) ? amap_final(r) : r;
    }

    const int ra = lane >> 2, ka = lane & 3;
    const uint32_t* Ah32 = (const uint32_t*)&Ahi[0][0];
    const uint32_t* Al32 = (const uint32_t*)&Alo[0][0];
    const int abase0 = (warp_m * 32 + ra) * 20 + ka;   // word index; row = 20 words

    // ldmatrix lane addressing: tiles (k0,n0),(k8,n0),(k0,n8),(k8,n8)
    const int tile = lane >> 3, trow = lane & 7;
    const int brow = (tile & 1) * 8 + trow;
    const int bcol = warp_n * 64 + (tile >> 1) * 8;
    const uint32_t bhi_base = smem_u32(&Bhi[brow][bcol]);
    const uint32_t blo_base = smem_u32(&Blo[brow][bcol]);

    for (int k0 = 0; k0 < K; k0 += 32) {
        __syncthreads();
        // ---- stage A tile (128 x 32 fp32 -> bf16 hi/lo) ----
#pragma unroll
        for (int i = 0; i < 4; i++) {
            int e = tid + i * 256;
            int row = e >> 3, c4 = (e & 7) * 4;
            float4 v = make_float4(0.f, 0.f, 0.f, 0.f);
            if (aval[i]) v = *(const float4*)(A + (size_t)arow_g[i] * K + k0 + c4);
            __nv_bfloat16 hx = __float2bfloat16(v.x), hy = __float2bfloat16(v.y);
            __nv_bfloat16 hz = __float2bfloat16(v.z), hw = __float2bfloat16(v.w);
            __nv_bfloat16 lx = __float2bfloat16(v.x - __bfloat162float(hx));
            __nv_bfloat16 ly = __float2bfloat16(v.y - __bfloat162float(hy));
            __nv_bfloat16 lz = __float2bfloat16(v.z - __bfloat162float(hz));
            __nv_bfloat16 lw = __float2bfloat16(v.w - __bfloat162float(hw));
            uint2 uh = make_uint2(pack_bf2(hx, hy), pack_bf2(hz, hw));
            uint2 ul = make_uint2(pack_bf2(lx, ly), pack_bf2(lz, lw));
            *(uint2*)&Ahi[row][c4] = uh;
            *(uint2*)&Alo[row][c4] = ul;
        }
        // ---- stage B tile (32 x 128 fp32 -> bf16 hi/lo) ----
#pragma unroll
        for (int i = 0; i < 4; i++) {
            int e = tid + i * 256;
            int row = e >> 5, c4 = (e & 31) * 4;
            float4 v = *(const float4*)(B + (size_t)(k0 + row) * N + bn + c4);
            __nv_bfloat16 hx = __float2bfloat16(v.x), hy = __float2bfloat16(v.y);
            __nv_bfloat16 hz = __float2bfloat16(v.z), hw = __float2bfloat16(v.w);
            __nv_bfloat16 lx = __float2bfloat16(v.x - __bfloat162float(hx));
            __nv_bfloat16 ly = __float2bfloat16(v.y - __bfloat162float(hy));
            __nv_bfloat16 lz = __float2bfloat16(v.z - __bfloat162float(hz));
            __nv_bfloat16 lw = __float2bfloat16(v.w - __bfloat162float(hw));
            uint2 uh = make_uint2(pack_bf2(hx, hy), pack_bf2(hz, hw));
            uint2 ul = make_uint2(pack_bf2(lx, ly), pack_bf2(lz, lw));
            *(uint2*)&Bhi[row][c4] = uh;
            *(uint2*)&Blo[row][c4] = ul;
        }
        __syncthreads();

#pragma unroll
        for (int kk = 0; kk < 2; kk++) {
            uint32_t ah[2][4], al[2][4];
#pragma unroll
            for (int mf = 0; mf < 2; mf++) {
                int b = abase0 + mf * 320 + kk * 8;
                ah[mf][0] = Ah32[b];       ah[mf][1] = Ah32[b + 160];
                ah[mf][2] = Ah32[b + 4];   ah[mf][3] = Ah32[b + 164];
                al[mf][0] = Al32[b];       al[mf][1] = Al32[b + 160];
                al[mf][2] = Al32[b + 4];   al[mf][3] = Al32[b + 164];
            }
#pragma unroll
            for (int j = 0; j < 4; j++) {
                uint32_t bh[4], bl[4];
                uint32_t off = kk * 16 * 272 + j * 32;   // 16 rows * 272B, 16 cols * 2B
                ldmat4t(bh, bhi_base + off);
                ldmat4t(bl, blo_base + off);
#pragma unroll
                for (int h = 0; h < 2; h++) {
#pragma unroll
                    for (int mf = 0; mf < 2; mf++) {
                        float* c = acc[mf * 8 + j * 2 + h];
                        mma16816(c, ah[mf], &bh[h * 2]);
                        mma16816(c, ah[mf], &bl[h * 2]);
                        mma16816(c, al[mf], &bh[h * 2]);
                    }
                }
            }
        }
    }

    // ---- epilogue ----
#pragma unroll
    for (int mf = 0; mf < 2; mf++) {
#pragma unroll
        for (int nf = 0; nf < 8; nf++) {
            const float* c = acc[mf * 8 + nf];
            int col = bn + warp_n * 64 + nf * 8 + ka * 2;
            int gr0 = bm + warp_m * 32 + mf * 16 + ra;
            int gr1 = gr0 + 8;
            if (gr0 < M) {
                int cr = (CMODE == 1) ? ((gr0 >> 6) * 65 + 1 + (gr0 & 63)) : gr0;
                *(float2*)&C[(size_t)cr * N + col] = make_float2(c[0], c[1]);
            }
            if (gr1 < M) {
                int cr = (CMODE == 1) ? ((gr1 >> 6) * 65 + 1 + (gr1 & 63)) : gr1;
                *(float2*)&C[(size_t)cr * N + col] = make_float2(c[2], c[3]);
            }
        }
    }
}

// ---------------------------------------------------------------------------
// comp GEMM: fx = x.reshape(32, 65536) @ W_comp (fp32 split-K, memory-bound)
// ---------------------------------------------------------------------------
__global__ __launch_bounds__(256)
void comp_kernel(const float* __restrict__ x, const float* __restrict__ Wc,
                 float* __restrict__ fxpart)
{
    __shared__ float As[32][33];
    const int tid = threadIdx.x;
    const int n = blockIdx.y * 512 + tid * 2;
    const int kbase = blockIdx.x * 512;
    const int slice = blockIdx.x;

    float2 acc[32];
#pragma unroll
    for (int m = 0; m < 32; m++) acc[m] = make_float2(0.f, 0.f);

    for (int k0 = kbase; k0 < kbase + 512; k0 += 32) {
        __syncthreads();
#pragma unroll
        for (int s = 0; s < 4; s++) {
            int i = s * 256 + tid;
            int m = i >> 5, kc = i & 31;
            As[m][kc] = x[m * 65536 + k0 + kc];
        }
        __syncthreads();
#pragma unroll 8
        for (int kc = 0; kc < 32; kc++) {
            float2 w = *(const float2*)&Wc[(size_t)(k0 + kc) * 1024 + n];
#pragma unroll
            for (int m = 0; m < 32; m++) {
                float a = As[m][kc];
                acc[m].x += a * w.x;
                acc[m].y += a * w.y;
            }
        }
    }
#pragma unroll
    for (int m = 0; m < 32; m++) {
        float* dst = &fxpart[(size_t)(slice * 32 + m) * 1024 + n];
        dst[0] = acc[m].x;
        dst[1] = acc[m].y;
    }
}

__global__ void fx_finalize(const float* __restrict__ fxpart,
                            const float* __restrict__ dummy,
                            const float* __restrict__ bias,
                            float* __restrict__ h)
{
    int c = blockIdx.x;
    int n = threadIdx.x;
    float v;
    if (c == 0) {
        v = dummy[n];
    } else {
        int m = c - 1;
        float s = bias[n];
        for (int sl = 0; sl < KSLICES; sl++)
            s += fxpart[(size_t)(sl * 32 + m) * 1024 + n];
        v = s;
    }
    int hrow = (c < 32) ? c * 65 : 2080;
    h[(size_t)hrow * CATD + n] = v;
}

// ---------------------------------------------------------------------------
// RoPE (in-place on q,k of g_qkv)
// ---------------------------------------------------------------------------
__global__ void rope_kernel(float* __restrict__ qkv,
                            const float* __restrict__ cosb,
                            const float* __restrict__ sinb)
{
    int gid = blockIdx.x * blockDim.x + threadIdx.x;
    if (gid >= S_LEN * NHEAD * 32) return;
    int i = gid & 31;
    int head = (gid >> 5) & 15;
    int pos = gid >> 9;
    float c0 = cosb[pos * 64 + i],      s0 = sinb[pos * 64 + i];
    float c1 = cosb[pos * 64 + i + 32], s1 = sinb[pos * 64 + i + 32];
    size_t base = (size_t)pos * 3072 + head * 64;
#pragma unroll
    for (int part = 0; part < 2; part++) {
        float* p = qkv + base + part * 1024;
        float a = p[i], b = p[i + 32];
        p[i]      = a * c0 - b * s0;
        p[i + 32] = b * c1 + a * s1;
    }
}

// ---------------------------------------------------------------------------
// Sparse CAT attention (unchanged)
// ---------------------------------------------------------------------------
__global__ __launch_bounds__(256)
void attn_kernel(const float* __restrict__ qkv, float* __restrict__ y)
{
    __shared__ float sprob[8][104];
    const int cq = blockIdx.x;
    const int head = blockIdx.y;
    const int warp = threadIdx.x >> 5;
    const int lane = threadIdx.x & 31;
    const int cnt = (cq == 32) ? 1 : 65;

    for (int j = warp; j < cnt; j += 8) {
        const int p = cq * 65 + j;
        float2 q2 = *(const float2*)(qkv + (size_t)p * 3072 + head * 64 + 2 * lane);
        const int nkeys = cq + j + 1;

        float mx = -1e30f;
        for (int kk = 0; kk < nkeys; kk++) {
            int kp = (kk < cq) ? kk * 65 : cq * 65 + (kk - cq);
            float2 k2 = *(const float2*)(qkv + (size_t)kp * 3072 + 1024 + head * 64 + 2 * lane);
            float s = q2.x * k2.x + q2.y * k2.y;
            s += __shfl_xor_sync(0xffffffffu, s, 16);
            s += __shfl_xor_sync(0xffffffffu, s, 8);
            s += __shfl_xor_sync(0xffffffffu, s, 4);
            s += __shfl_xor_sync(0xffffffffu, s, 2);
            s += __shfl_xor_sync(0xffffffffu, s, 1);
            s *= 0.125f;
            if (lane == 0) sprob[warp][kk] = s;
            mx = fmaxf(mx, s);
        }
        __syncwarp();

        float sum = 0.f;
        for (int kk = lane; kk < nkeys; kk += 32) {
            float e = __expf(sprob[warp][kk] - mx);
            sprob[warp][kk] = e;
            sum += e;
        }
        sum += __shfl_xor_sync(0xffffffffu, sum, 16);
        sum += __shfl_xor_sync(0xffffffffu, sum, 8);
        sum += __shfl_xor_sync(0xffffffffu, sum, 4);
        sum += __shfl_xor_sync(0xffffffffu, sum, 2);
        sum += __shfl_xor_sync(0xffffffffu, sum, 1);
        __syncwarp();
        float inv = 1.f / sum;

        float2 acc = make_float2(0.f, 0.f);
        for (int kk = 0; kk < nkeys; kk++) {
            int kp = (kk < cq) ? kk * 65 : cq * 65 + (kk - cq);
            float pr = sprob[warp][kk];
            float2 v2 = *(const float2*)(qkv + (size_t)kp * 3072 + 2048 + head * 64 + 2 * lane);
            acc.x += pr * v2.x;
            acc.y += pr * v2.y;
        }
        float2 o = make_float2(acc.x * inv, acc.y * inv);
        *(float2*)(y + (size_t)p * 1024 + head * 64 + 2 * lane) = o;
        __syncwarp();
    }
}

// ---------------------------------------------------------------------------
extern "C" void kernel_launch(void* const* d_in, const int* in_sizes, int n_in,
                              void* d_out, int out_size)
{
    const float* x        = (const float*)d_in[0];
    const float* W_expand = (const float*)d_in[1];
    const float* W_comp   = (const float*)d_in[2];
    const float* b_comp   = (const float*)d_in[3];
    const float* dummy_fx = (const float*)d_in[4];
    const float* W_qkv    = (const float*)d_in[5];
    const float* W_o      = (const float*)d_in[6];
    const float* W_final  = (const float*)d_in[7];
    const float* cosb     = (const float*)d_in[8];
    const float* sinb     = (const float*)d_in[9];
    float* out = (float*)d_out;

    float *fxpart, *h, *qkv, *y, *y2;
    cudaGetSymbolAddress((void**)&fxpart, g_fxpart);
    cudaGetSymbolAddress((void**)&h,      g_h);
    cudaGetSymbolAddress((void**)&qkv,    g_qkv);
    cudaGetSymbolAddress((void**)&y,      g_y);
    cudaGetSymbolAddress((void**)&y2,     g_y2);

    // 1. fx partials (split-K, deterministic)
    comp_kernel<<<dim3(KSLICES, 2), 256>>>(x, W_comp, fxpart);

    // 2. reduce partials -> anchor rows of h
    fx_finalize<<<33, 1024>>>(fxpart, dummy_fx, b_comp, h);

    // 3. xe = x @ W_expand, scattered into non-anchor rows of h
    mma_gemm<0, 1><<<dim3(8, 16), 256>>>(x, W_expand, h, 2048, 1024, 1024);

    // 4. qkv = h @ W_qkv
    mma_gemm<0, 0><<<dim3(24, 17), 256>>>(h, W_qkv, qkv, S_LEN, 3072, 1024);

    // 5. RoPE on q and k
    rope_kernel<<<(S_LEN * NHEAD * 32 + 255) / 256, 256>>>(qkv, cosb, sinb);

    // 6. sparse CAT attention
    attn_kernel<<<dim3(33, 16), 256>>>(qkv, y);

    // 7. y2 = y @ W_o
    mma_gemm<0, 0><<<dim3(8, 17), 256>>>(y, W_o, y2, S_LEN, 1024, 1024);

    // 8. out = gather(y2) @ W_final
    mma_gemm<1, 0><<<dim3(8, 16), 256>>>(y2, W_final, out, 2048, 1024, 1024);
}

// round 3
// speedup vs baseline: 2.0676x; 1.1004x over previous
#include <cuda_runtime.h>
#include <cuda_bf16.h>
#include <math.h>
#include <stdint.h>

// ---------------------------------------------------------------------------
// CAT_Attention (B=1, BLOCK=2048, CHUNK=64, DIM=1024, CAT=1024, NH=16, HD=64)
// S = 2081, W = 65, NC = 32
// Round 3: bf16 hi/lo operands pre-converted in global; cp.async double-
// buffered mma pipeline; parallel fx reduction; restructured comp kernel.
// ---------------------------------------------------------------------------

#define S_LEN   2081
#define CATD    1024
#define NHEAD   16
#define CSLICES 64

typedef __nv_bfloat16 bf16;
typedef __nv_bfloat162 bf162;

// -------------------- scratch (device globals; no allocs) -------------------
__device__ float g_fxpart[CSLICES * 32 * 1024];        // 8 MB
__device__ float g_qkv [S_LEN * 3 * CATD];             // fp32 (rope/attn)
__device__ bf16  g_xhi[2048 * 1024],  g_xlo[2048 * 1024];
__device__ bf16  g_hhi[S_LEN * 1024], g_hlo[S_LEN * 1024];
__device__ bf16  g_yhi[S_LEN * 1024], g_ylo[S_LEN * 1024];
__device__ bf16  g_y2hi[S_LEN * 1024], g_y2lo[S_LEN * 1024];
__device__ bf16  g_wexphi[1024 * 1024], g_wexplo[1024 * 1024];
__device__ bf16  g_wqkvhi[1024 * 3072], g_wqkvlo[1024 * 3072];
__device__ bf16  g_wohi[1024 * 1024],   g_wolo[1024 * 1024];
__device__ bf16  g_wfinhi[1024 * 1024], g_wfinlo[1024 * 1024];

// -------------------- row maps ---------------------------------------------
__device__ __forceinline__ int amap_final(int r) {
    if (r < 63)    return r + 1;
    if (r == 2047) return 2080;
    int u = r - 63;
    return 65 + u + (u >> 6);
}

// -------------------- helpers ----------------------------------------------
__device__ __forceinline__ uint32_t smem_u32(const void* p) {
    return (uint32_t)__cvta_generic_to_shared(p);
}

__device__ __forceinline__ void cp16(uint32_t dst, const void* src) {
    asm volatile("cp.async.cg.shared.global [%0], [%1], 16;\n" :: "r"(dst), "l"(src));
}

__device__ __forceinline__ void mma16816(float* c, const uint32_t* a, const uint32_t* b) {
    asm volatile(
        "mma.sync.aligned.m16n8k16.row.col.f32.bf16.bf16.f32 "
        "{%0,%1,%2,%3}, {%4,%5,%6,%7}, {%8,%9}, {%0,%1,%2,%3};"
        : "+f"(c[0]), "+f"(c[1]), "+f"(c[2]), "+f"(c[3])
        : "r"(a[0]), "r"(a[1]), "r"(a[2]), "r"(a[3]), "r"(b[0]), "r"(b[1]));
}

__device__ __forceinline__ void ldmat4(uint32_t* r, uint32_t addr) {
    asm volatile(
        "ldmatrix.sync.aligned.m8n8.x4.shared.b16 {%0,%1,%2,%3}, [%4];"
        : "=r"(r[0]), "=r"(r[1]), "=r"(r[2]), "=r"(r[3]) : "r"(addr));
}

__device__ __forceinline__ void ldmat4t(uint32_t* r, uint32_t addr) {
    asm volatile(
        "ldmatrix.sync.aligned.m8n8.x4.trans.shared.b16 {%0,%1,%2,%3}, [%4];"
        : "=r"(r[0]), "=r"(r[1]), "=r"(r[2]), "=r"(r[3]) : "r"(addr));
}

__device__ __forceinline__ void st_bf16pair(bf16* hi, bf16* lo, size_t idx,
                                            float v0, float v1) {
    bf16 h0 = __float2bfloat16(v0), h1 = __float2bfloat16(v1);
    bf16 l0 = __float2bfloat16(v0 - __bfloat162float(h0));
    bf16 l1 = __float2bfloat16(v1 - __bfloat162float(h1));
    *(bf162*)(hi + idx) = __halves2bfloat162(h0, h1);
    *(bf162*)(lo + idx) = __halves2bfloat162(l0, l1);
}

// ---------------------------------------------------------------------------
// convert fp32 -> bf16 hi/lo (grid-stride over float4 groups)
// ---------------------------------------------------------------------------
__global__ void cvt_kernel(const float* __restrict__ src, bf16* __restrict__ hi,
                           bf16* __restrict__ lo, int n4)
{
    int i = blockIdx.x * blockDim.x + threadIdx.x;
    if (i >= n4) return;
    float4 v = ((const float4*)src)[i];
    bf16 h0 = __float2bfloat16(v.x), h1 = __float2bfloat16(v.y);
    bf16 h2 = __float2bfloat16(v.z), h3 = __float2bfloat16(v.w);
    bf162 hh0 = __halves2bfloat162(h0, h1), hh1 = __halves2bfloat162(h2, h3);
    bf162 ll0 = __halves2bfloat162(__float2bfloat16(v.x - __bfloat162float(h0)),
                                   __float2bfloat16(v.y - __bfloat162float(h1)));
    bf162 ll1 = __halves2bfloat162(__float2bfloat16(v.z - __bfloat162float(h2)),
                                   __float2bfloat16(v.w - __bfloat162float(h3)));
    uint2 uh = make_uint2(*(uint32_t*)&hh0, *(uint32_t*)&hh1);
    uint2 ul = make_uint2(*(uint32_t*)&ll0, *(uint32_t*)&ll1);
    *(uint2*)(hi + 4 * (size_t)i) = uh;
    *(uint2*)(lo + 4 * (size_t)i) = ul;
}

// ---------------------------------------------------------------------------
// Tensor-core GEMM v2: bf16 hi/lo operands from global; cp.async pipeline.
// Tile 128x128x32, 2 stages, 256 threads (8 warps 4x2), warp tile 32x64.
// AMODE: 0 identity rows, 1 gather amap_final.
// CMODE: 0 fp32 C, 1 bf16 hi/lo scatter into h, 2 bf16 hi/lo identity.
// ---------------------------------------------------------------------------
#define A_LO_OFF 10240u
#define B_HI_OFF 20480u
#define B_LO_OFF 29184u
#define STAGE_SZ 37888u
#define DSMEM    75776

template<int AMODE, int CMODE>
__global__ __launch_bounds__(256, 2)
void mma_gemm(const bf16* __restrict__ Agh, const bf16* __restrict__ Agl,
              const bf16* __restrict__ Bgh, const bf16* __restrict__ Bgl,
              float* __restrict__ C, bf16* __restrict__ Chi, bf16* __restrict__ Clo,
              int M, int N, int K)
{
    extern __shared__ char dsm[];
    const uint32_t sb = smem_u32(dsm);
    const int tid = threadIdx.x, lane = tid & 31, wid = tid >> 5;
    const int warp_m = wid & 3, warp_n = wid >> 2;
    const int bm = blockIdx.y * 128, bn = blockIdx.x * 128;

    // cp.async source offsets
    size_t aoff[2];
#pragma unroll
    for (int i = 0; i < 2; i++) {
        int gr = bm + (tid >> 2) + i * 64;
        int r = (gr < M) ? gr : 0;
        if (AMODE == 1) r = amap_final(r);
        aoff[i] = (size_t)r * K + (tid & 3) * 8;
    }
    const uint32_t a_dst = (tid >> 2) * 80 + (tid & 3) * 16;
    const int b_row = tid >> 4;
    const size_t b_col = (size_t)bn + (tid & 15) * 8;
    const uint32_t b_dst = (tid >> 4) * 272 + (tid & 15) * 16;

    // fragment smem addresses
    const int quad = lane >> 3, lrow = lane & 7;
    const uint32_t a_frag = (uint32_t)((warp_m * 32 + (quad & 1) * 8 + lrow) * 80 + (quad >> 1) * 16);
    const uint32_t b_frag = (uint32_t)(((quad & 1) * 8 + lrow) * 272 + (warp_n * 64 + (quad >> 1) * 8) * 2);

    float acc[16][4];
#pragma unroll
    for (int i = 0; i < 16; i++)
#pragma unroll
        for (int j = 0; j < 4; j++) acc[i][j] = 0.f;

    const int NIT = K >> 5;

    auto issue = [&](int it) {
        const int k0 = it << 5;
        const uint32_t st = sb + (uint32_t)(it & 1) * STAGE_SZ;
#pragma unroll
        for (int i = 0; i < 2; i++) {
            cp16(st + a_dst + i * 5120u,            Agh + aoff[i] + k0);
            cp16(st + A_LO_OFF + a_dst + i * 5120u, Agl + aoff[i] + k0);
        }
#pragma unroll
        for (int i = 0; i < 2; i++) {
            size_t src = (size_t)(k0 + b_row + i * 16) * N + b_col;
            cp16(st + B_HI_OFF + b_dst + i * 4352u, Bgh + src);
            cp16(st + B_LO_OFF + b_dst + i * 4352u, Bgl + src);
        }
        asm volatile("cp.async.commit_group;\n" ::: "memory");
    };

    issue(0);
    for (int it = 0; it < NIT; it++) {
        if (it + 1 < NIT) {
            issue(it + 1);
            asm volatile("cp.async.wait_group 1;\n" ::: "memory");
        } else {
            asm volatile("cp.async.wait_group 0;\n" ::: "memory");
        }
        __syncthreads();
        const uint32_t st = sb + (uint32_t)(it & 1) * STAGE_SZ;
#pragma unroll
        for (int kk = 0; kk < 2; kk++) {
            uint32_t ah[2][4], al[2][4];
#pragma unroll
            for (int mf = 0; mf < 2; mf++) {
                ldmat4(ah[mf], st + a_frag + mf * 1280u + kk * 32u);
                ldmat4(al[mf], st + A_LO_OFF + a_frag + mf * 1280u + kk * 32u);
            }
#pragma unroll
            for (int j = 0; j < 4; j++) {
                uint32_t bh[4], bl[4];
                ldmat4t(bh, st + B_HI_OFF + b_frag + kk * 4352u + j * 32u);
                ldmat4t(bl, st + B_LO_OFF + b_frag + kk * 4352u + j * 32u);
#pragma unroll
                for (int h = 0; h < 2; h++)
#pragma unroll
                    for (int mf = 0; mf < 2; mf++) {
                        float* c = acc[mf * 8 + j * 2 + h];
                        mma16816(c, ah[mf], &bh[h * 2]);
                        mma16816(c, ah[mf], &bl[h * 2]);
                        mma16816(c, al[mf], &bh[h * 2]);
                    }
            }
        }
        __syncthreads();
    }

    // epilogue
    const int ra = lane >> 2, ka = lane & 3;
#pragma unroll
    for (int mf = 0; mf < 2; mf++)
#pragma unroll
        for (int nf = 0; nf < 8; nf++) {
            const float* c = acc[mf * 8 + nf];
            int col = bn + warp_n * 64 + nf * 8 + ka * 2;
#pragma unroll
            for (int h = 0; h < 2; h++) {
                int gr = bm + warp_m * 32 + mf * 16 + ra + h * 8;
                if (gr >= M) continue;
                float v0 = c[h * 2], v1 = c[h * 2 + 1];
                if (CMODE == 0) {
                    *(float2*)&C[(size_t)gr * N + col] = make_float2(v0, v1);
                } else {
                    int cr = (CMODE == 1) ? ((gr >> 6) * 65 + 1 + (gr & 63)) : gr;
                    st_bf16pair(Chi, Clo, (size_t)cr * N + col, v0, v1);
                }
            }
        }
}

// ---------------------------------------------------------------------------
// comp GEMM: fx = x.reshape(32, 65536) @ W_comp  (fp32 split-K)
// grid (64 slices, 2 rowgroups); 16 rows x 4 cols per thread.
// ---------------------------------------------------------------------------
__global__ __launch_bounds__(256)
void comp_kernel(const float* __restrict__ x, const float* __restrict__ Wc,
                 float* __restrict__ fxpart)
{
    __shared__ float As[16][33];
    const int tid = threadIdx.x;
    const int slice = blockIdx.x;
    const int rg = blockIdx.y;
    const int n = tid * 4;
    const int kbase = slice * 1024;

    float4 acc[16];
#pragma unroll
    for (int m = 0; m < 16; m++) acc[m] = make_float4(0.f, 0.f, 0.f, 0.f);

    for (int k0 = kbase; k0 < kbase + 1024; k0 += 32) {
        __syncthreads();
#pragma unroll
        for (int s = 0; s < 2; s++) {
            int i = tid + s * 256;
            As[i >> 5][i & 31] = x[(size_t)(rg * 16 + (i >> 5)) * 65536 + k0 + (i & 31)];
        }
        __syncthreads();
#pragma unroll 4
        for (int kc = 0; kc < 32; kc++) {
            float4 w = *(const float4*)&Wc[(size_t)(k0 + kc) * 1024 + n];
#pragma unroll
            for (int m = 0; m < 16; m++) {
                float a = As[m][kc];
                acc[m].x += a * w.x; acc[m].y += a * w.y;
                acc[m].z += a * w.z; acc[m].w += a * w.w;
            }
        }
    }
#pragma unroll
    for (int m = 0; m < 16; m++)
        *(float4*)&fxpart[(size_t)(slice * 32 + rg * 16 + m) * 1024 + n] = acc[m];
}

// reduce partials (+bias / dummy) -> bf16 hi/lo anchor rows of h
__global__ void fx_reduce(const float* __restrict__ fxpart,
                          const float* __restrict__ dummy,
                          const float* __restrict__ bias,
                          bf16* __restrict__ hhi, bf16* __restrict__ hlo)
{
    int col = blockIdx.x * 128 + threadIdx.x;
    int c = blockIdx.y;          // 0..32
    float v;
    if (c == 0) {
        v = dummy[col];
    } else {
        int m = c - 1;
        float s = bias[col];
#pragma unroll 8
        for (int sl = 0; sl < CSLICES; sl++)
            s += fxpart[(size_t)(sl * 32 + m) * 1024 + col];
        v = s;
    }
    int hrow = (c < 32) ? c * 65 : 2080;
    bf16 h = __float2bfloat16(v);
    hhi[(size_t)hrow * CATD + col] = h;
    hlo[(size_t)hrow * CATD + col] = __float2bfloat16(v - __bfloat162float(h));
}

// ---------------------------------------------------------------------------
// RoPE (in-place on fp32 qkv)
// ---------------------------------------------------------------------------
__global__ void rope_kernel(float* __restrict__ qkv,
                            const float* __restrict__ cosb,
                            const float* __restrict__ sinb)
{
    int gid = blockIdx.x * blockDim.x + threadIdx.x;
    if (gid >= S_LEN * NHEAD * 32) return;
    int i = gid & 31;
    int head = (gid >> 5) & 15;
    int pos = gid >> 9;
    float c0 = cosb[pos * 64 + i],      s0 = sinb[pos * 64 + i];
    float c1 = cosb[pos * 64 + i + 32], s1 = sinb[pos * 64 + i + 32];
    size_t base = (size_t)pos * 3072 + head * 64;
#pragma unroll
    for (int part = 0; part < 2; part++) {
        float* p = qkv + base + part * 1024;
        float a = p[i], b = p[i + 32];
        p[i]      = a * c0 - b * s0;
        p[i + 32] = b * c1 + a * s1;
    }
}

// ---------------------------------------------------------------------------
// Sparse CAT attention -> writes y as bf16 hi/lo
// ---------------------------------------------------------------------------
__global__ __launch_bounds__(256)
void attn_kernel(const float* __restrict__ qkv,
                 bf16* __restrict__ yhi, bf16* __restrict__ ylo)
{
    __shared__ float sprob[8][104];
    const int cq = blockIdx.x;
    const int head = blockIdx.y;
    const int warp = threadIdx.x >> 5;
    const int lane = threadIdx.x & 31;
    const int cnt = (cq == 32) ? 1 : 65;

    for (int j = warp; j < cnt; j += 8) {
        const int p = cq * 65 + j;
        float2 q2 = *(const float2*)(qkv + (size_t)p * 3072 + head * 64 + 2 * lane);
        const int nkeys = cq + j + 1;

        float mx = -1e30f;
        for (int kk = 0; kk < nkeys; kk++) {
            int kp = (kk < cq) ? kk * 65 : cq * 65 + (kk - cq);
            float2 k2 = *(const float2*)(qkv + (size_t)kp * 3072 + 1024 + head * 64 + 2 * lane);
            float s = q2.x * k2.x + q2.y * k2.y;
            s += __shfl_xor_sync(0xffffffffu, s, 16);
            s += __shfl_xor_sync(0xffffffffu, s, 8);
            s += __shfl_xor_sync(0xffffffffu, s, 4);
            s += __shfl_xor_sync(0xffffffffu, s, 2);
            s += __shfl_xor_sync(0xffffffffu, s, 1);
            s *= 0.125f;
            if (lane == 0) sprob[warp][kk] = s;
            mx = fmaxf(mx, s);
        }
        __syncwarp();

        float sum = 0.f;
        for (int kk = lane; kk < nkeys; kk += 32) {
            float e = __expf(sprob[warp][kk] - mx);
            sprob[warp][kk] = e;
            sum += e;
        }
        sum += __shfl_xor_sync(0xffffffffu, sum, 16);
        sum += __shfl_xor_sync(0xffffffffu, sum, 8);
        sum += __shfl_xor_sync(0xffffffffu, sum, 4);
        sum += __shfl_xor_sync(0xffffffffu, sum, 2);
        sum += __shfl_xor_sync(0xffffffffu, sum, 1);
        __syncwarp();
        float inv = 1.f / sum;

        float2 acc = make_float2(0.f, 0.f);
        for (int kk = 0; kk < nkeys; kk++) {
            int kp = (kk < cq) ? kk * 65 : cq * 65 + (kk - cq);
            float pr = sprob[warp][kk];
            float2 v2 = *(const float2*)(qkv + (size_t)kp * 3072 + 2048 + head * 64 + 2 * lane);
            acc.x += pr * v2.x;
            acc.y += pr * v2.y;
        }
        st_bf16pair(yhi, ylo, (size_t)p * CATD + head * 64 + 2 * lane,
                    acc.x * inv, acc.y * inv);
        __syncwarp();
    }
}

// ---------------------------------------------------------------------------
extern "C" void kernel_launch(void* const* d_in, const int* in_sizes, int n_in,
                              void* d_out, int out_size)
{
    const float* x        = (const float*)d_in[0];
    const float* W_expand = (const float*)d_in[1];
    const float* W_comp   = (const float*)d_in[2];
    const float* b_comp   = (const float*)d_in[3];
    const float* dummy_fx = (const float*)d_in[4];
    const float* W_qkv    = (const float*)d_in[5];
    const float* W_o      = (const float*)d_in[6];
    const float* W_final  = (const float*)d_in[7];
    const float* cosb     = (const float*)d_in[8];
    const float* sinb     = (const float*)d_in[9];
    float* out = (float*)d_out;

    float *fxpart, *qkv;
    bf16 *xhi, *xlo, *hhi, *hlo, *yhi, *ylo, *y2hi, *y2lo;
    bf16 *wexphi, *wexplo, *wqkvhi, *wqkvlo, *wohi, *wolo, *wfinhi, *wfinlo;
    cudaGetSymbolAddress((void**)&fxpart, g_fxpart);
    cudaGetSymbolAddress((void**)&qkv,    g_qkv);
    cudaGetSymbolAddress((void**)&xhi,    g_xhi);
    cudaGetSymbolAddress((void**)&xlo,    g_xlo);
    cudaGetSymbolAddress((void**)&hhi,    g_hhi);
    cudaGetSymbolAddress((void**)&hlo,    g_hlo);
    cudaGetSymbolAddress((void**)&yhi,    g_yhi);
    cudaGetSymbolAddress((void**)&ylo,    g_ylo);
    cudaGetSymbolAddress((void**)&y2hi,   g_y2hi);
    cudaGetSymbolAddress((void**)&y2lo,   g_y2lo);
    cudaGetSymbolAddress((void**)&wexphi, g_wexphi);
    cudaGetSymbolAddress((void**)&wexplo, g_wexplo);
    cudaGetSymbolAddress((void**)&wqkvhi, g_wqkvhi);
    cudaGetSymbolAddress((void**)&wqkvlo, g_wqkvlo);
    cudaGetSymbolAddress((void**)&wohi,   g_wohi);
    cudaGetSymbolAddress((void**)&wolo,   g_wolo);
    cudaGetSymbolAddress((void**)&wfinhi, g_wfinhi);
    cudaGetSymbolAddress((void**)&wfinlo, g_wfinlo);

    cudaFuncSetAttribute(mma_gemm<0, 1>, cudaFuncAttributeMaxDynamicSharedMemorySize, DSMEM);
    cudaFuncSetAttribute(mma_gemm<0, 0>, cudaFuncAttributeMaxDynamicSharedMemorySize, DSMEM);
    cudaFuncSetAttribute(mma_gemm<0, 2>, cudaFuncAttributeMaxDynamicSharedMemorySize, DSMEM);
    cudaFuncSetAttribute(mma_gemm<1, 0>, cudaFuncAttributeMaxDynamicSharedMemorySize, DSMEM);

    // 0. convert x + weights to bf16 hi/lo
    cvt_kernel<<<2048, 256>>>(x,        xhi,    xlo,    524288);
    cvt_kernel<<<1024, 256>>>(W_expand, wexphi, wexplo, 262144);
    cvt_kernel<<<3072, 256>>>(W_qkv,    wqkvhi, wqkvlo, 786432);
    cvt_kernel<<<1024, 256>>>(W_o,      wohi,   wolo,   262144);
    cvt_kernel<<<1024, 256>>>(W_final,  wfinhi, wfinlo, 262144);

    // 1. fx partials (fp32 split-K)
    comp_kernel<<<dim3(CSLICES, 2), 256>>>(x, W_comp, fxpart);

    // 2. reduce partials -> bf16 anchor rows of h
    fx_reduce<<<dim3(8, 33), 128>>>(fxpart, dummy_fx, b_comp, hhi, hlo);

    // 3. xe = x @ W_expand -> scattered bf16 rows of h
    mma_gemm<0, 1><<<dim3(8, 16), 256, DSMEM>>>(xhi, xlo, wexphi, wexplo,
                                                nullptr, hhi, hlo, 2048, 1024, 1024);

    // 4. qkv = h @ W_qkv (fp32 out)
    mma_gemm<0, 0><<<dim3(24, 17), 256, DSMEM>>>(hhi, hlo, wqkvhi, wqkvlo,
                                                 qkv, nullptr, nullptr, S_LEN, 3072, 1024);

    // 5. RoPE
    rope_kernel<<<(S_LEN * NHEAD * 32 + 255) / 256, 256>>>(qkv, cosb, sinb);

    // 6. sparse CAT attention -> bf16 y
    attn_kernel<<<dim3(33, 16), 256>>>(qkv, yhi, ylo);

    // 7. y2 = y @ W_o (bf16 out)
    mma_gemm<0, 2><<<dim3(8, 17), 256, DSMEM>>>(yhi, ylo, wohi, wolo,
                                                nullptr, y2hi, y2lo, S_LEN, 1024, 1024);

    // 8. out = gather(y2) @ W_final (fp32 out)
    mma_gemm<1, 0><<<dim3(8, 16), 256, DSMEM>>>(y2hi, y2lo, wfinhi, wfinlo,
                                                out, nullptr, nullptr, 2048, 1024, 1024);
}

// round 4
// speedup vs baseline: 2.9787x; 1.4407x over previous
#include <cuda_runtime.h>
#include <cuda_bf16.h>
#include <math.h>
#include <stdint.h>

// ---------------------------------------------------------------------------
// CAT_Attention (B=1, BLOCK=2048, CHUNK=64, DIM=1024, CAT=1024, NH=16, HD=64)
// S = 2081, W = 65, NC = 32
// Round 4: comp GEMM on tensor cores (inline fp32->bf16 hi/lo of W_comp);
// attention v2 with smem-staged K/V and key-per-lane scoring.
// ---------------------------------------------------------------------------

#define S_LEN   2081
#define CATD    1024
#define NHEAD   16
#define CSLICES 64

typedef __nv_bfloat16 bf16;
typedef __nv_bfloat162 bf162;

// -------------------- scratch (device globals; no allocs) -------------------
__device__ float g_fxpart[CSLICES * 32 * 1024];
__device__ float g_qkv [S_LEN * 3 * CATD];
__device__ bf16  g_xhi[2048 * 1024],  g_xlo[2048 * 1024];
__device__ bf16  g_hhi[S_LEN * 1024], g_hlo[S_LEN * 1024];
__device__ bf16  g_yhi[S_LEN * 1024], g_ylo[S_LEN * 1024];
__device__ bf16  g_y2hi[S_LEN * 1024], g_y2lo[S_LEN * 1024];
__device__ bf16  g_wexphi[1024 * 1024], g_wexplo[1024 * 1024];
__device__ bf16  g_wqkvhi[1024 * 3072], g_wqkvlo[1024 * 3072];
__device__ bf16  g_wohi[1024 * 1024],   g_wolo[1024 * 1024];
__device__ bf16  g_wfinhi[1024 * 1024], g_wfinlo[1024 * 1024];

// -------------------- row maps ---------------------------------------------
__device__ __forceinline__ int amap_final(int r) {
    if (r < 63)    return r + 1;
    if (r == 2047) return 2080;
    int u = r - 63;
    return 65 + u + (u >> 6);
}

// -------------------- helpers ----------------------------------------------
__device__ __forceinline__ uint32_t smem_u32(const void* p) {
    return (uint32_t)__cvta_generic_to_shared(p);
}

__device__ __forceinline__ void cp16(uint32_t dst, const void* src) {
    asm volatile("cp.async.cg.shared.global [%0], [%1], 16;\n" :: "r"(dst), "l"(src));
}

__device__ __forceinline__ void mma16816(float* c, const uint32_t* a, const uint32_t* b) {
    asm volatile(
        "mma.sync.aligned.m16n8k16.row.col.f32.bf16.bf16.f32 "
        "{%0,%1,%2,%3}, {%4,%5,%6,%7}, {%8,%9}, {%0,%1,%2,%3};"
        : "+f"(c[0]), "+f"(c[1]), "+f"(c[2]), "+f"(c[3])
        : "r"(a[0]), "r"(a[1]), "r"(a[2]), "r"(a[3]), "r"(b[0]), "r"(b[1]));
}

__device__ __forceinline__ void ldmat4(uint32_t* r, uint32_t addr) {
    asm volatile(
        "ldmatrix.sync.aligned.m8n8.x4.shared.b16 {%0,%1,%2,%3}, [%4];"
        : "=r"(r[0]), "=r"(r[1]), "=r"(r[2]), "=r"(r[3]) : "r"(addr));
}

__device__ __forceinline__ void ldmat4t(uint32_t* r, uint32_t addr) {
    asm volatile(
        "ldmatrix.sync.aligned.m8n8.x4.trans.shared.b16 {%0,%1,%2,%3}, [%4];"
        : "=r"(r[0]), "=r"(r[1]), "=r"(r[2]), "=r"(r[3]) : "r"(addr));
}

__device__ __forceinline__ void split2(float a, float b, uint32_t& hi, uint32_t& lo) {
    bf16 h0 = __float2bfloat16(a), h1 = __float2bfloat16(b);
    bf16 l0 = __float2bfloat16(a - __bfloat162float(h0));
    bf16 l1 = __float2bfloat16(b - __bfloat162float(h1));
    bf162 hh = __halves2bfloat162(h0, h1), ll = __halves2bfloat162(l0, l1);
    hi = *(uint32_t*)&hh; lo = *(uint32_t*)&ll;
}

__device__ __forceinline__ void st_bf16pair(bf16* hi, bf16* lo, size_t idx,
                                            float v0, float v1) {
    uint32_t h, l;
    split2(v0, v1, h, l);
    *(uint32_t*)(hi + idx) = h;
    *(uint32_t*)(lo + idx) = l;
}

// ---------------------------------------------------------------------------
// convert fp32 -> bf16 hi/lo
// ---------------------------------------------------------------------------
__global__ void cvt_kernel(const float* __restrict__ src, bf16* __restrict__ hi,
                           bf16* __restrict__ lo, int n4)
{
    int i = blockIdx.x * blockDim.x + threadIdx.x;
    if (i >= n4) return;
    float4 v = ((const float4*)src)[i];
    uint2 uh, ul;
    split2(v.x, v.y, uh.x, ul.x);
    split2(v.z, v.w, uh.y, ul.y);
    *(uint2*)(hi + 4 * (size_t)i) = uh;
    *(uint2*)(lo + 4 * (size_t)i) = ul;
}

// ---------------------------------------------------------------------------
// Tensor-core GEMM (dense layers): bf16 hi/lo operands, cp.async 2-stage.
// ---------------------------------------------------------------------------
#define A_LO_OFF 10240u
#define B_HI_OFF 20480u
#define B_LO_OFF 29184u
#define STAGE_SZ 37888u
#define DSMEM    75776

template<int AMODE, int CMODE>
__global__ __launch_bounds__(256, 2)
void mma_gemm(const bf16* __restrict__ Agh, const bf16* __restrict__ Agl,
              const bf16* __restrict__ Bgh, const bf16* __restrict__ Bgl,
              float* __restrict__ C, bf16* __restrict__ Chi, bf16* __restrict__ Clo,
              int M, int N, int K)
{
    extern __shared__ char dsm[];
    const uint32_t sb = smem_u32(dsm);
    const int tid = threadIdx.x, lane = tid & 31, wid = tid >> 5;
    const int warp_m = wid & 3, warp_n = wid >> 2;
    const int bm = blockIdx.y * 128, bn = blockIdx.x * 128;

    size_t aoff[2];
#pragma unroll
    for (int i = 0; i < 2; i++) {
        int gr = bm + (tid >> 2) + i * 64;
        int r = (gr < M) ? gr : 0;
        if (AMODE == 1) r = amap_final(r);
        aoff[i] = (size_t)r * K + (tid & 3) * 8;
    }
    const uint32_t a_dst = (tid >> 2) * 80 + (tid & 3) * 16;
    const int b_row = tid >> 4;
    const size_t b_col = (size_t)bn + (tid & 15) * 8;
    const uint32_t b_dst = (tid >> 4) * 272 + (tid & 15) * 16;

    const int quad = lane >> 3, lrow = lane & 7;
    const uint32_t a_frag = (uint32_t)((warp_m * 32 + (quad & 1) * 8 + lrow) * 80 + (quad >> 1) * 16);
    const uint32_t b_frag = (uint32_t)(((quad & 1) * 8 + lrow) * 272 + (warp_n * 64 + (quad >> 1) * 8) * 2);

    float acc[16][4];
#pragma unroll
    for (int i = 0; i < 16; i++)
#pragma unroll
        for (int j = 0; j < 4; j++) acc[i][j] = 0.f;

    const int NIT = K >> 5;

    auto issue = [&](int it) {
        const int k0 = it << 5;
        const uint32_t st = sb + (uint32_t)(it & 1) * STAGE_SZ;
#pragma unroll
        for (int i = 0; i < 2; i++) {
            cp16(st + a_dst + i * 5120u,            Agh + aoff[i] + k0);
            cp16(st + A_LO_OFF + a_dst + i * 5120u, Agl + aoff[i] + k0);
        }
#pragma unroll
        for (int i = 0; i < 2; i++) {
            size_t src = (size_t)(k0 + b_row + i * 16) * N + b_col;
            cp16(st + B_HI_OFF + b_dst + i * 4352u, Bgh + src);
            cp16(st + B_LO_OFF + b_dst + i * 4352u, Bgl + src);
        }
        asm volatile("cp.async.commit_group;\n" ::: "memory");
    };

    issue(0);
    for (int it = 0; it < NIT; it++) {
        if (it + 1 < NIT) {
            issue(it + 1);
            asm volatile("cp.async.wait_group 1;\n" ::: "memory");
        } else {
            asm volatile("cp.async.wait_group 0;\n" ::: "memory");
        }
        __syncthreads();
        const uint32_t st = sb + (uint32_t)(it & 1) * STAGE_SZ;
#pragma unroll
        for (int kk = 0; kk < 2; kk++) {
            uint32_t ah[2][4], al[2][4];
#pragma unroll
            for (int mf = 0; mf < 2; mf++) {
                ldmat4(ah[mf], st + a_frag + mf * 1280u + kk * 32u);
                ldmat4(al[mf], st + A_LO_OFF + a_frag + mf * 1280u + kk * 32u);
            }
#pragma unroll
            for (int j = 0; j < 4; j++) {
                uint32_t bh[4], bl[4];
                ldmat4t(bh, st + B_HI_OFF + b_frag + kk * 4352u + j * 32u);
                ldmat4t(bl, st + B_LO_OFF + b_frag + kk * 4352u + j * 32u);
#pragma unroll
                for (int h = 0; h < 2; h++)
#pragma unroll
                    for (int mf = 0; mf < 2; mf++) {
                        float* c = acc[mf * 8 + j * 2 + h];
                        mma16816(c, ah[mf], &bh[h * 2]);
                        mma16816(c, ah[mf], &bl[h * 2]);
                        mma16816(c, al[mf], &bh[h * 2]);
                    }
            }
        }
        __syncthreads();
    }

    const int ra = lane >> 2, ka = lane & 3;
#pragma unroll
    for (int mf = 0; mf < 2; mf++)
#pragma unroll
        for (int nf = 0; nf < 8; nf++) {
            const float* c = acc[mf * 8 + nf];
            int col = bn + warp_n * 64 + nf * 8 + ka * 2;
#pragma unroll
            for (int h = 0; h < 2; h++) {
                int gr = bm + warp_m * 32 + mf * 16 + ra + h * 8;
                if (gr >= M) continue;
                float v0 = c[h * 2], v1 = c[h * 2 + 1];
                if (CMODE == 0) {
                    *(float2*)&C[(size_t)gr * N + col] = make_float2(v0, v1);
                } else {
                    int cr = (CMODE == 1) ? ((gr >> 6) * 65 + 1 + (gr & 63)) : gr;
                    st_bf16pair(Chi, Clo, (size_t)cr * N + col, v0, v1);
                }
            }
        }
}

// ---------------------------------------------------------------------------
// comp GEMM v3 (tensor cores): fx = x.reshape(32,65536) @ W_comp, split-K.
// Grid (8 N-tiles, 64 K-slices). M=32 whole per block; W converted inline.
// ---------------------------------------------------------------------------
__global__ __launch_bounds__(256)
void comp_kernel(const bf16* __restrict__ xhi, const bf16* __restrict__ xlo,
                 const float* __restrict__ Wc, float* __restrict__ fxpart)
{
    __shared__ bf16 Ahi[32][40], Alo[32][40];
    __shared__ bf16 Bhi[32][136], Blo[32][136];

    const int tid = threadIdx.x, lane = tid & 31, warp = tid >> 5;
    const int bn = blockIdx.x * 128;
    const int kb = blockIdx.y * 1024;

    const int wr = tid >> 3, wc = (tid & 7) * 16;   // W: 32 rows x 128 cols
    const int xr = tid >> 3, xc = (tid & 7) * 4;    // x: 32 rows x 32 cols

    float4 wreg[4];
    uint2 xh, xl;
    auto loadNext = [&](int k0) {
        const float* wp = Wc + (size_t)(kb + k0 + wr) * 1024 + bn + wc;
#pragma unroll
        for (int i = 0; i < 4; i++) wreg[i] = *(const float4*)(wp + i * 4);
        size_t xoff = (size_t)xr * 65536 + kb + k0 + xc;
        xh = *(const uint2*)(xhi + xoff);
        xl = *(const uint2*)(xlo + xoff);
    };

    float acc[2][2][4];
#pragma unroll
    for (int i = 0; i < 2; i++)
#pragma unroll
        for (int j = 0; j < 2; j++)
#pragma unroll
            for (int q = 0; q < 4; q++) acc[i][j][q] = 0.f;

    const uint32_t ah_base = smem_u32(&Ahi[0][0]);
    const uint32_t al_base = smem_u32(&Alo[0][0]);
    const uint32_t bh_base = smem_u32(&Bhi[0][0]);
    const uint32_t bl_base = smem_u32(&Blo[0][0]);
    const int quad = lane >> 3, lrow = lane & 7;
    const uint32_t a_off = (uint32_t)(((quad & 1) * 8 + lrow) * 80 + (quad >> 1) * 16);
    const uint32_t b_off = (uint32_t)(((quad & 1) * 8 + lrow) * 272 + (warp * 16 + (quad >> 1) * 8) * 2);

    loadNext(0);
    for (int k0 = 0; k0 < 1024; k0 += 32) {
        __syncthreads();
#pragma unroll
        for (int i = 0; i < 4; i++) {
            float4 v = wreg[i];
            uint2 uh, ul;
            split2(v.x, v.y, uh.x, ul.x);
            split2(v.z, v.w, uh.y, ul.y);
            *(uint2*)&Bhi[wr][wc + i * 4] = uh;
            *(uint2*)&Blo[wr][wc + i * 4] = ul;
        }
        *(uint2*)&Ahi[xr][xc] = xh;
        *(uint2*)&Alo[xr][xc] = xl;
        __syncthreads();
        if (k0 + 32 < 1024) loadNext(k0 + 32);

#pragma unroll
        for (int kk = 0; kk < 2; kk++) {
            uint32_t ah[2][4], al[2][4], bh[4], bl[4];
#pragma unroll
            for (int mf = 0; mf < 2; mf++) {
                ldmat4(ah[mf], ah_base + mf * 1280u + a_off + kk * 32u);
                ldmat4(al[mf], al_base + mf * 1280u + a_off + kk * 32u);
            }
            ldmat4t(bh, bh_base + b_off + kk * 4352u);
            ldmat4t(bl, bl_base + b_off + kk * 4352u);
#pragma unroll
            for (int nf = 0; nf < 2; nf++)
#pragma unroll
                for (int mf = 0; mf < 2; mf++) {
                    float* c = acc[mf][nf];
                    mma16816(c, ah[mf], &bh[nf * 2]);
                    mma16816(c, ah[mf], &bl[nf * 2]);
                    mma16816(c, al[mf], &bh[nf * 2]);
                }
        }
    }

    const int ra = lane >> 2, ka = lane & 3;
#pragma unroll
    for (int mf = 0; mf < 2; mf++)
#pragma unroll
        for (int nf = 0; nf < 2; nf++)
#pragma unroll
            for (int h = 0; h < 2; h++) {
                int row = mf * 16 + ra + h * 8;
                int col = bn + warp * 16 + nf * 8 + ka * 2;
                *(float2*)&fxpart[(size_t)(blockIdx.y * 32 + row) * 1024 + col] =
                    make_float2(acc[mf][nf][h * 2], acc[mf][nf][h * 2 + 1]);
            }
}

// reduce partials (+bias / dummy) -> bf16 hi/lo anchor rows of h
__global__ void fx_reduce(const float* __restrict__ fxpart,
                          const float* __restrict__ dummy,
                          const float* __restrict__ bias,
                          bf16* __restrict__ hhi, bf16* __restrict__ hlo)
{
    int col = blockIdx.x * 128 + threadIdx.x;
    int c = blockIdx.y;
    float v;
    if (c == 0) {
        v = dummy[col];
    } else {
        int m = c - 1;
        float s = bias[col];
#pragma unroll 8
        for (int sl = 0; sl < CSLICES; sl++)
            s += fxpart[(size_t)(sl * 32 + m) * 1024 + col];
        v = s;
    }
    int hrow = (c < 32) ? c * 65 : 2080;
    bf16 h = __float2bfloat16(v);
    hhi[(size_t)hrow * CATD + col] = h;
    hlo[(size_t)hrow * CATD + col] = __float2bfloat16(v - __bfloat162float(h));
}

// ---------------------------------------------------------------------------
// RoPE (in-place on fp32 qkv)
// ---------------------------------------------------------------------------
__global__ void rope_kernel(float* __restrict__ qkv,
                            const float* __restrict__ cosb,
                            const float* __restrict__ sinb)
{
    int gid = blockIdx.x * blockDim.x + threadIdx.x;
    if (gid >= S_LEN * NHEAD * 32) return;
    int i = gid & 31;
    int head = (gid >> 5) & 15;
    int pos = gid >> 9;
    float c0 = cosb[pos * 64 + i],      s0 = sinb[pos * 64 + i];
    float c1 = cosb[pos * 64 + i + 32], s1 = sinb[pos * 64 + i + 32];
    size_t base = (size_t)pos * 3072 + head * 64;
#pragma unroll
    for (int part = 0; part < 2; part++) {
        float* p = qkv + base + part * 1024;
        float a = p[i], b = p[i + 32];
        p[i]      = a * c0 - b * s0;
        p[i + 32] = b * c1 + a * s1;
    }
}

// ---------------------------------------------------------------------------
// Sparse CAT attention v2: K/V staged in smem, key-per-lane scores.
// grid (33, 16); 256 threads = 8 warps, one query per warp.
// ---------------------------------------------------------------------------
#define KPAD 68
#define ATTN_SMEM ((97 * KPAD * 2 + 8 * 64 + 8 * 100) * 4)

__global__ __launch_bounds__(256)
void attn_kernel(const float* __restrict__ qkv,
                 bf16* __restrict__ yhi, bf16* __restrict__ ylo)
{
    extern __shared__ float dyn[];
    float* sK = dyn;
    float* sV = sK + 97 * KPAD;
    float* sq = sV + 97 * KPAD;
    float* sp = sq + 8 * 64;

    const int cq = blockIdx.x;
    const int head = blockIdx.y;
    const int tid = threadIdx.x;
    const int warp = tid >> 5, lane = tid & 31;
    const int cnt = (cq == 32) ? 1 : 65;
    const int total = cq + cnt;

    // stage K and V rows for all keys this block can touch
    for (int idx = tid; idx < total * 16; idx += 256) {
        int kk = idx >> 4, seg = idx & 15;
        int kp = (kk < cq) ? kk * 65 : cq * 65 + (kk - cq);
        const float* base = qkv + (size_t)kp * 3072 + head * 64 + seg * 4;
        float4 kv = *(const float4*)(base + 1024);
        float4 vv = *(const float4*)(base + 2048);
        *(float4*)&sK[kk * KPAD + seg * 4] = kv;
        *(float4*)&sV[kk * KPAD + seg * 4] = vv;
    }
    __syncthreads();

    for (int j = warp; j < cnt; j += 8) {
        const int p = cq * 65 + j;
        const int nk = cq + j + 1;

        float2 q2 = *(const float2*)(qkv + (size_t)p * 3072 + head * 64 + 2 * lane);
        sq[warp * 64 + 2 * lane]     = q2.x;
        sq[warp * 64 + 2 * lane + 1] = q2.y;
        __syncwarp();

        // scores: one key per lane
        float mx = -1e30f;
        for (int kb2 = 0; kb2 < nk; kb2 += 32) {
            int kk = kb2 + lane;
            float s = -1e30f;
            if (kk < nk) {
                float a = 0.f;
#pragma unroll
                for (int d4 = 0; d4 < 16; d4++) {
                    float4 qv = *(const float4*)&sq[warp * 64 + d4 * 4];
                    float4 kv = *(const float4*)&sK[kk * KPAD + d4 * 4];
                    a += qv.x * kv.x + qv.y * kv.y + qv.z * kv.z + qv.w * kv.w;
                }
                s = a * 0.125f;
                sp[warp * 100 + kk] = s;
            }
            mx = fmaxf(mx, s);
        }
        mx = fmaxf(mx, __shfl_xor_sync(0xffffffffu, mx, 16));
        mx = fmaxf(mx, __shfl_xor_sync(0xffffffffu, mx, 8));
        mx = fmaxf(mx, __shfl_xor_sync(0xffffffffu, mx, 4));
        mx = fmaxf(mx, __shfl_xor_sync(0xffffffffu, mx, 2));
        mx = fmaxf(mx, __shfl_xor_sync(0xffffffffu, mx, 1));
        __syncwarp();

        float sum = 0.f;
        for (int kk = lane; kk < nk; kk += 32) {
            float e = __expf(sp[warp * 100 + kk] - mx);
            sp[warp * 100 + kk] = e;
            sum += e;
        }
        sum += __shfl_xor_sync(0xffffffffu, sum, 16);
        sum += __shfl_xor_sync(0xffffffffu, sum, 8);
        sum += __shfl_xor_sync(0xffffffffu, sum, 4);
        sum += __shfl_xor_sync(0xffffffffu, sum, 2);
        sum += __shfl_xor_sync(0xffffffffu, sum, 1);
        __syncwarp();
        float inv = 1.f / sum;

        float2 acc = make_float2(0.f, 0.f);
        for (int kk = 0; kk < nk; kk++) {
            float pr = sp[warp * 100 + kk];
            float2 v2 = *(const float2*)&sV[kk * KPAD + 2 * lane];
            acc.x += pr * v2.x;
            acc.y += pr * v2.y;
        }
        st_bf16pair(yhi, ylo, (size_t)p * CATD + head * 64 + 2 * lane,
                    acc.x * inv, acc.y * inv);
        __syncwarp();
    }
}

// ---------------------------------------------------------------------------
extern "C" void kernel_launch(void* const* d_in, const int* in_sizes, int n_in,
                              void* d_out, int out_size)
{
    const float* x        = (const float*)d_in[0];
    const float* W_expand = (const float*)d_in[1];
    const float* W_comp   = (const float*)d_in[2];
    const float* b_comp   = (const float*)d_in[3];
    const float* dummy_fx = (const float*)d_in[4];
    const float* W_qkv    = (const float*)d_in[5];
    const float* W_o      = (const float*)d_in[6];
    const float* W_final  = (const float*)d_in[7];
    const float* cosb     = (const float*)d_in[8];
    const float* sinb     = (const float*)d_in[9];
    float* out = (float*)d_out;

    float *fxpart, *qkv;
    bf16 *xhi, *xlo, *hhi, *hlo, *yhi, *ylo, *y2hi, *y2lo;
    bf16 *wexphi, *wexplo, *wqkvhi, *wqkvlo, *wohi, *wolo, *wfinhi, *wfinlo;
    cudaGetSymbolAddress((void**)&fxpart, g_fxpart);
    cudaGetSymbolAddress((void**)&qkv,    g_qkv);
    cudaGetSymbolAddress((void**)&xhi,    g_xhi);
    cudaGetSymbolAddress((void**)&xlo,    g_xlo);
    cudaGetSymbolAddress((void**)&hhi,    g_hhi);
    cudaGetSymbolAddress((void**)&hlo,    g_hlo);
    cudaGetSymbolAddress((void**)&yhi,    g_yhi);
    cudaGetSymbolAddress((void**)&ylo,    g_ylo);
    cudaGetSymbolAddress((void**)&y2hi,   g_y2hi);
    cudaGetSymbolAddress((void**)&y2lo,   g_y2lo);
    cudaGetSymbolAddress((void**)&wexphi, g_wexphi);
    cudaGetSymbolAddress((void**)&wexplo, g_wexplo);
    cudaGetSymbolAddress((void**)&wqkvhi, g_wqkvhi);
    cudaGetSymbolAddress((void**)&wqkvlo, g_wqkvlo);
    cudaGetSymbolAddress((void**)&wohi,   g_wohi);
    cudaGetSymbolAddress((void**)&wolo,   g_wolo);
    cudaGetSymbolAddress((void**)&wfinhi, g_wfinhi);
    cudaGetSymbolAddress((void**)&wfinlo, g_wfinlo);

    cudaFuncSetAttribute(mma_gemm<0, 1>, cudaFuncAttributeMaxDynamicSharedMemorySize, DSMEM);
    cudaFuncSetAttribute(mma_gemm<0, 0>, cudaFuncAttributeMaxDynamicSharedMemorySize, DSMEM);
    cudaFuncSetAttribute(mma_gemm<0, 2>, cudaFuncAttributeMaxDynamicSharedMemorySize, DSMEM);
    cudaFuncSetAttribute(mma_gemm<1, 0>, cudaFuncAttributeMaxDynamicSharedMemorySize, DSMEM);
    cudaFuncSetAttribute(attn_kernel,    cudaFuncAttributeMaxDynamicSharedMemorySize, ATTN_SMEM);

    // 0. convert x + weights to bf16 hi/lo
    cvt_kernel<<<2048, 256>>>(x,        xhi,    xlo,    524288);
    cvt_kernel<<<1024, 256>>>(W_expand, wexphi, wexplo, 262144);
    cvt_kernel<<<3072, 256>>>(W_qkv,    wqkvhi, wqkvlo, 786432);
    cvt_kernel<<<1024, 256>>>(W_o,      wohi,   wolo,   262144);
    cvt_kernel<<<1024, 256>>>(W_final,  wfinhi, wfinlo, 262144);

    // 1. fx partials (tensor-core split-K, inline W conversion)
    comp_kernel<<<dim3(8, CSLICES), 256>>>(xhi, xlo, W_comp, fxpart);

    // 2. reduce partials -> bf16 anchor rows of h
    fx_reduce<<<dim3(8, 33), 128>>>(fxpart, dummy_fx, b_comp, hhi, hlo);

    // 3. xe = x @ W_expand -> scattered bf16 rows of h
    mma_gemm<0, 1><<<dim3(8, 16), 256, DSMEM>>>(xhi, xlo, wexphi, wexplo,
                                                nullptr, hhi, hlo, 2048, 1024, 1024);

    // 4. qkv = h @ W_qkv (fp32 out)
    mma_gemm<0, 0><<<dim3(24, 17), 256, DSMEM>>>(hhi, hlo, wqkvhi, wqkvlo,
                                                 qkv, nullptr, nullptr, S_LEN, 3072, 1024);

    // 5. RoPE
    rope_kernel<<<(S_LEN * NHEAD * 32 + 255) / 256, 256>>>(qkv, cosb, sinb);

    // 6. sparse CAT attention -> bf16 y
    attn_kernel<<<dim3(33, 16), 256, ATTN_SMEM>>>(qkv, yhi, ylo);

    // 7. y2 = y @ W_o (bf16 out)
    mma_gemm<0, 2><<<dim3(8, 17), 256, DSMEM>>>(yhi, ylo, wohi, wolo,
                                                nullptr, y2hi, y2lo, S_LEN, 1024, 1024);

    // 8. out = gather(y2) @ W_final (fp32 out)
    mma_gemm<1, 0><<<dim3(8, 16), 256, DSMEM>>>(y2hi, y2lo, wfinhi, wfinlo,
                                                out, nullptr, nullptr, 2048, 1024, 1024);
}

// round 7
// speedup vs baseline: 3.1776x; 1.0667x over previous
#include <cuda_runtime.h>
#include <cuda_bf16.h>
#include <math.h>
#include <stdint.h>

// ---------------------------------------------------------------------------
// CAT_Attention (B=1, BLOCK=2048, CHUNK=64, DIM=1024, CAT=1024, NH=16, HD=64)
// S = 2081, W = 65, NC = 32
// Round 7 (= round 5 design, third submit after two broker failures):
// GEMM engine v3 (XOR-swizzled smem, 3-stage cp.async, 1 sync/iter);
// RoPE fused into qkv epilogue.
// ---------------------------------------------------------------------------

#define S_LEN   2081
#define CATD    1024
#define NHEAD   16
#define CSLICES 64

typedef __nv_bfloat16 bf16;
typedef __nv_bfloat162 bf162;

// -------------------- scratch (device globals; no allocs) -------------------
__device__ float g_fxpart[CSLICES * 32 * 1024];
__device__ float g_qkv [S_LEN * 3 * CATD];
__device__ bf16  g_xhi[2048 * 1024],  g_xlo[2048 * 1024];
__device__ bf16  g_hhi[S_LEN * 1024], g_hlo[S_LEN * 1024];
__device__ bf16  g_yhi[S_LEN * 1024], g_ylo[S_LEN * 1024];
__device__ bf16  g_y2hi[S_LEN * 1024], g_y2lo[S_LEN * 1024];
__device__ bf16  g_wexphi[1024 * 1024], g_wexplo[1024 * 1024];
__device__ bf16  g_wqkvhi[1024 * 3072], g_wqkvlo[1024 * 3072];
__device__ bf16  g_wohi[1024 * 1024],   g_wolo[1024 * 1024];
__device__ bf16  g_wfinhi[1024 * 1024], g_wfinlo[1024 * 1024];

// -------------------- row maps ---------------------------------------------
__device__ __forceinline__ int amap_final(int r) {
    if (r < 63)    return r + 1;
    if (r == 2047) return 2080;
    int u = r - 63;
    return 65 + u + (u >> 6);
}

// -------------------- helpers ----------------------------------------------
__device__ __forceinline__ uint32_t smem_u32(const void* p) {
    return (uint32_t)__cvta_generic_to_shared(p);
}

__device__ __forceinline__ void cp16(uint32_t dst, const void* src) {
    asm volatile("cp.async.cg.shared.global [%0], [%1], 16;\n" :: "r"(dst), "l"(src));
}

__device__ __forceinline__ void mma16816(float* c, const uint32_t* a, const uint32_t* b) {
    asm volatile(
        "mma.sync.aligned.m16n8k16.row.col.f32.bf16.bf16.f32 "
        "{%0,%1,%2,%3}, {%4,%5,%6,%7}, {%8,%9}, {%0,%1,%2,%3};"
        : "+f"(c[0]), "+f"(c[1]), "+f"(c[2]), "+f"(c[3])
        : "r"(a[0]), "r"(a[1]), "r"(a[2]), "r"(a[3]), "r"(b[0]), "r"(b[1]));
}

__device__ __forceinline__ void ldmat4(uint32_t* r, uint32_t addr) {
    asm volatile(
        "ldmatrix.sync.aligned.m8n8.x4.shared.b16 {%0,%1,%2,%3}, [%4];"
        : "=r"(r[0]), "=r"(r[1]), "=r"(r[2]), "=r"(r[3]) : "r"(addr));
}

__device__ __forceinline__ void ldmat4t(uint32_t* r, uint32_t addr) {
    asm volatile(
        "ldmatrix.sync.aligned.m8n8.x4.trans.shared.b16 {%0,%1,%2,%3}, [%4];"
        : "=r"(r[0]), "=r"(r[1]), "=r"(r[2]), "=r"(r[3]) : "r"(addr));
}

__device__ __forceinline__ void split2(float a, float b, uint32_t& hi, uint32_t& lo) {
    bf16 h0 = __float2bfloat16(a), h1 = __float2bfloat16(b);
    bf16 l0 = __float2bfloat16(a - __bfloat162float(h0));
    bf16 l1 = __float2bfloat16(b - __bfloat162float(h1));
    bf162 hh = __halves2bfloat162(h0, h1), ll = __halves2bfloat162(l0, l1);
    hi = *(uint32_t*)&hh; lo = *(uint32_t*)&ll;
}

__device__ __forceinline__ void st_bf16pair(bf16* hi, bf16* lo, size_t idx,
                                            float v0, float v1) {
    uint32_t h, l;
    split2(v0, v1, h, l);
    *(uint32_t*)(hi + idx) = h;
    *(uint32_t*)(lo + idx) = l;
}

// ---------------------------------------------------------------------------
// convert fp32 -> bf16 hi/lo
// ---------------------------------------------------------------------------
__global__ void cvt_kernel(const float* __restrict__ src, bf16* __restrict__ hi,
                           bf16* __restrict__ lo, int n4)
{
    int i = blockIdx.x * blockDim.x + threadIdx.x;
    if (i >= n4) return;
    float4 v = ((const float4*)src)[i];
    uint2 uh, ul;
    split2(v.x, v.y, uh.x, ul.x);
    split2(v.z, v.w, uh.y, ul.y);
    *(uint2*)(hi + 4 * (size_t)i) = uh;
    *(uint2*)(lo + 4 * (size_t)i) = ul;
}

// ---------------------------------------------------------------------------
// GEMM engine v3: XOR-swizzled smem, 3-stage cp.async, 1 __syncthreads/iter.
// Tile 128x128x32, 256 threads (8 warps 4x2), warp tile 32x64.
// AMODE: 0 identity, 1 gather amap_final.
// CMODE: 0 fp32 C, 1 bf16 scatter->h, 2 bf16 identity, 3 fp32 + fused RoPE.
// Stage layout: Ahi@0 Alo@8192 Bhi@16384 Blo@24576, stage=32768, 3 stages.
// ---------------------------------------------------------------------------
#define STAGE_SZ 32768u
#define DSMEM    98304

template<int AMODE, int CMODE>
__global__ __launch_bounds__(256, 2)
void mma_gemm(const bf16* __restrict__ Agh, const bf16* __restrict__ Agl,
              const bf16* __restrict__ Bgh, const bf16* __restrict__ Bgl,
              float* __restrict__ C, bf16* __restrict__ Chi, bf16* __restrict__ Clo,
              const float* __restrict__ cosb, const float* __restrict__ sinb,
              int M, int N, int K)
{
    extern __shared__ char dsm[];
    const uint32_t sb = smem_u32(dsm);
    const int tid = threadIdx.x, lane = tid & 31, wid = tid >> 5;
    const int warp_m = wid & 3, warp_n = wid >> 2;
    const int bm = blockIdx.y * 128, bn = blockIdx.x * 128;

    // ---- cp.async source/dest (swizzled) ----
    size_t aoff[2];
#pragma unroll
    for (int i = 0; i < 2; i++) {
        int gr = bm + (tid >> 2) + i * 64;
        int r = (gr < M) ? gr : 0;
        if (AMODE == 1) r = amap_final(r);
        aoff[i] = (size_t)r * K + (tid & 3) * 8;
    }
    const int arow0 = tid >> 2;
    const uint32_t aswz = (uint32_t)(((tid & 3) ^ ((arow0 >> 1) & 3)) << 4);
    uint32_t a_dst[2];
#pragma unroll
    for (int i = 0; i < 2; i++) a_dst[i] = (uint32_t)((arow0 + i * 64) * 64) + aswz;

    const int krow0 = tid >> 4;
    const size_t b_col = (size_t)bn + (tid & 15) * 8;
    const uint32_t bswz = (uint32_t)((((tid & 15) ^ (krow0 & 7))) << 4);
    uint32_t b_dst[2];
#pragma unroll
    for (int i = 0; i < 2; i++) b_dst[i] = (uint32_t)((krow0 + i * 16) * 256) + bswz;

    // ---- ldmatrix addressing (swizzled, per-lane) ----
    const int quad = lane >> 3, lrow = lane & 7;
    const int c2 = quad >> 1;
    const int rowLocal = (quad & 1) * 8 + lrow;
    const uint32_t aRowByte = (uint32_t)((warp_m * 32 + rowLocal) * 64);
    const int swA = (rowLocal >> 1) & 3;
    const uint32_t bRowByte = (uint32_t)(rowLocal * 256);

    float acc[16][4];
#pragma unroll
    for (int i = 0; i < 16; i++)
#pragma unroll
        for (int j = 0; j < 4; j++) acc[i][j] = 0.f;

    const int NIT = K >> 5;

    auto issue = [&](int it) {
        const int k0 = it << 5;
        const uint32_t st = sb + (uint32_t)(it % 3) * STAGE_SZ;
#pragma unroll
        for (int i = 0; i < 2; i++) {
            cp16(st + a_dst[i],         Agh + aoff[i] + k0);
            cp16(st + 8192u + a_dst[i], Agl + aoff[i] + k0);
        }
#pragma unroll
        for (int i = 0; i < 2; i++) {
            size_t src = (size_t)(k0 + krow0 + i * 16) * N + b_col;
            cp16(st + 16384u + b_dst[i], Bgh + src);
            cp16(st + 24576u + b_dst[i], Bgl + src);
        }
        asm volatile("cp.async.commit_group;\n" ::: "memory");
    };

    issue(0);
    issue(1);
    for (int it = 0; it < NIT; it++) {
        if (it + 1 < NIT)
            asm volatile("cp.async.wait_group 1;\n" ::: "memory");
        else
            asm volatile("cp.async.wait_group 0;\n" ::: "memory");
        __syncthreads();
        if (it + 2 < NIT) issue(it + 2);

        const uint32_t st = sb + (uint32_t)(it % 3) * STAGE_SZ;
#pragma unroll
        for (int kk = 0; kk < 2; kk++) {
            uint32_t ah[2][4], al[2][4];
#pragma unroll
            for (int mf = 0; mf < 2; mf++) {
                uint32_t achunk = (uint32_t)((((kk * 2 + c2) ^ swA)) << 4);
                uint32_t aaddr = st + aRowByte + (uint32_t)(mf * 1024) + achunk;
                ldmat4(ah[mf], aaddr);
                ldmat4(al[mf], aaddr + 8192u);
            }
            const uint32_t bk = st + 16384u + (uint32_t)(kk * 16 * 256) + bRowByte;
#pragma unroll
            for (int j = 0; j < 4; j++) {
                uint32_t bh[4], bl[4];
                uint32_t bchunk = (uint32_t)(((warp_n * 8 + c2 + j * 2) ^ lrow) << 4);
                ldmat4t(bh, bk + bchunk);
                ldmat4t(bl, bk + bchunk + 8192u);
#pragma unroll
                for (int h = 0; h < 2; h++)
#pragma unroll
                    for (int mf = 0; mf < 2; mf++) {
                        float* c = acc[mf * 8 + j * 2 + h];
                        mma16816(c, ah[mf], &bh[h * 2]);
                        mma16816(c, ah[mf], &bl[h * 2]);
                        mma16816(c, al[mf], &bh[h * 2]);
                    }
            }
        }
    }

    // ---- epilogue ----
    const int ra = lane >> 2, ka = lane & 3;
    const int colBase = bn + warp_n * 64;

    if (CMODE == 3 && colBase < 2048) {
        // fused RoPE on q/k: pair (d, d+32) lives in acc[nf] / acc[nf+4]
#pragma unroll
        for (int mf = 0; mf < 2; mf++)
#pragma unroll
            for (int hh = 0; hh < 2; hh++) {
                int gr = bm + warp_m * 32 + mf * 16 + ra + hh * 8;
                if (gr >= M) continue;
                const float* cb = cosb + (size_t)gr * 64;
                const float* sn = sinb + (size_t)gr * 64;
#pragma unroll
                for (int nf = 0; nf < 4; nf++) {
                    int d = nf * 8 + ka * 2;
                    float a0 = acc[mf * 8 + nf][hh * 2];
                    float a1 = acc[mf * 8 + nf][hh * 2 + 1];
                    float b0 = acc[mf * 8 + nf + 4][hh * 2];
                    float b1 = acc[mf * 8 + nf + 4][hh * 2 + 1];
                    float o0 = a0 * cb[d]     - b0 * sn[d];
                    float o1 = a1 * cb[d + 1] - b1 * sn[d + 1];
                    float p0 = b0 * cb[d + 32] + a0 * sn[d + 32];
                    float p1 = b1 * cb[d + 33] + a1 * sn[d + 33];
                    *(float2*)&C[(size_t)gr * N + colBase + d]      = make_float2(o0, o1);
                    *(float2*)&C[(size_t)gr * N + colBase + d + 32] = make_float2(p0, p1);
                }
            }
        return;
    }

#pragma unroll
    for (int mf = 0; mf < 2; mf++)
#pragma unroll
        for (int nf = 0; nf < 8; nf++) {
            const float* c = acc[mf * 8 + nf];
            int col = colBase + nf * 8 + ka * 2;
#pragma unroll
            for (int h = 0; h < 2; h++) {
                int gr = bm + warp_m * 32 + mf * 16 + ra + h * 8;
                if (gr >= M) continue;
                float v0 = c[h * 2], v1 = c[h * 2 + 1];
                if (CMODE == 0 || CMODE == 3) {
                    *(float2*)&C[(size_t)gr * N + col] = make_float2(v0, v1);
                } else {
                    int cr = (CMODE == 1) ? ((gr >> 6) * 65 + 1 + (gr & 63)) : gr;
                    st_bf16pair(Chi, Clo, (size_t)cr * N + col, v0, v1);
                }
            }
        }
}

// ---------------------------------------------------------------------------
// comp GEMM (tensor cores): fx = x.reshape(32,65536) @ W_comp, split-K.
// ---------------------------------------------------------------------------
__global__ __launch_bounds__(256)
void comp_kernel(const bf16* __restrict__ xhi, const bf16* __restrict__ xlo,
                 const float* __restrict__ Wc, float* __restrict__ fxpart)
{
    __shared__ bf16 Ahi[32][40], Alo[32][40];
    __shared__ bf16 Bhi[32][136], Blo[32][136];

    const int tid = threadIdx.x, lane = tid & 31, warp = tid >> 5;
    const int bn = blockIdx.x * 128;
    const int kb = blockIdx.y * 1024;

    const int wr = tid >> 3, wc = (tid & 7) * 16;
    const int xr = tid >> 3, xc = (tid & 7) * 4;

    float4 wreg[4];
    uint2 xh, xl;
    auto loadNext = [&](int k0) {
        const float* wp = Wc + (size_t)(kb + k0 + wr) * 1024 + bn + wc;
#pragma unroll
        for (int i = 0; i < 4; i++) wreg[i] = *(const float4*)(wp + i * 4);
        size_t xoff = (size_t)xr * 65536 + kb + k0 + xc;
        xh = *(const uint2*)(xhi + xoff);
        xl = *(const uint2*)(xlo + xoff);
    };

    float acc[2][2][4];
#pragma unroll
    for (int i = 0; i < 2; i++)
#pragma unroll
        for (int j = 0; j < 2; j++)
#pragma unroll
            for (int q = 0; q < 4; q++) acc[i][j][q] = 0.f;

    const uint32_t ah_base = smem_u32(&Ahi[0][0]);
    const uint32_t al_base = smem_u32(&Alo[0][0]);
    const uint32_t bh_base = smem_u32(&Bhi[0][0]);
    const uint32_t bl_base = smem_u32(&Blo[0][0]);
    const int quad = lane >> 3, lrow = lane & 7;
    const uint32_t a_off = (uint32_t)(((quad & 1) * 8 + lrow) * 80 + (quad >> 1) * 16);
    const uint32_t b_off = (uint32_t)(((quad & 1) * 8 + lrow) * 272 + (warp * 16 + (quad >> 1) * 8) * 2);

    loadNext(0);
    for (int k0 = 0; k0 < 1024; k0 += 32) {
        __syncthreads();
#pragma unroll
        for (int i = 0; i < 4; i++) {
            float4 v = wreg[i];
            uint2 uh, ul;
            split2(v.x, v.y, uh.x, ul.x);
            split2(v.z, v.w, uh.y, ul.y);
            *(uint2*)&Bhi[wr][wc + i * 4] = uh;
            *(uint2*)&Blo[wr][wc + i * 4] = ul;
        }
        *(uint2*)&Ahi[xr][xc] = xh;
        *(uint2*)&Alo[xr][xc] = xl;
        __syncthreads();
        if (k0 + 32 < 1024) loadNext(k0 + 32);

#pragma unroll
        for (int kk = 0; kk < 2; kk++) {
            uint32_t ah[2][4], al[2][4], bh[4], bl[4];
#pragma unroll
            for (int mf = 0; mf < 2; mf++) {
                ldmat4(ah[mf], ah_base + mf * 1280u + a_off + kk * 32u);
                ldmat4(al[mf], al_base + mf * 1280u + a_off + kk * 32u);
            }
            ldmat4t(bh, bh_base + b_off + kk * 4352u);
            ldmat4t(bl, bl_base + b_off + kk * 4352u);
#pragma unroll
            for (int nf = 0; nf < 2; nf++)
#pragma unroll
                for (int mf = 0; mf < 2; mf++) {
                    float* c = acc[mf][nf];
                    mma16816(c, ah[mf], &bh[nf * 2]);
                    mma16816(c, ah[mf], &bl[nf * 2]);
                    mma16816(c, al[mf], &bh[nf * 2]);
                }
        }
    }

    const int ra = lane >> 2, ka = lane & 3;
#pragma unroll
    for (int mf = 0; mf < 2; mf++)
#pragma unroll
        for (int nf = 0; nf < 2; nf++)
#pragma unroll
            for (int h = 0; h < 2; h++) {
                int row = mf * 16 + ra + h * 8;
                int col = bn + warp * 16 + nf * 8 + ka * 2;
                *(float2*)&fxpart[(size_t)(blockIdx.y * 32 + row) * 1024 + col] =
                    make_float2(acc[mf][nf][h * 2], acc[mf][nf][h * 2 + 1]);
            }
}

// reduce partials (+bias / dummy) -> bf16 hi/lo anchor rows of h
__global__ void fx_reduce(const float* __restrict__ fxpart,
                          const float* __restrict__ dummy,
                          const float* __restrict__ bias,
                          bf16* __restrict__ hhi, bf16* __restrict__ hlo)
{
    int col = blockIdx.x * 128 + threadIdx.x;
    int c = blockIdx.y;
    float v;
    if (c == 0) {
        v = dummy[col];
    } else {
        int m = c - 1;
        float s = bias[col];
#pragma unroll 8
        for (int sl = 0; sl < CSLICES; sl++)
            s += fxpart[(size_t)(sl * 32 + m) * 1024 + col];
        v = s;
    }
    int hrow = (c < 32) ? c * 65 : 2080;
    bf16 h = __float2bfloat16(v);
    hhi[(size_t)hrow * CATD + col] = h;
    hlo[(size_t)hrow * CATD + col] = __float2bfloat16(v - __bfloat162float(h));
}

// ---------------------------------------------------------------------------
// Sparse CAT attention: K/V staged in smem, key-per-lane scores.
// ---------------------------------------------------------------------------
#define KPAD 68
#define ATTN_SMEM ((97 * KPAD * 2 + 8 * 64 + 8 * 100) * 4)

__global__ __launch_bounds__(256)
void attn_kernel(const float* __restrict__ qkv,
                 bf16* __restrict__ yhi, bf16* __restrict__ ylo)
{
    extern __shared__ float dyn[];
    float* sK = dyn;
    float* sV = sK + 97 * KPAD;
    float* sq = sV + 97 * KPAD;
    float* sp = sq + 8 * 64;

    const int cq = blockIdx.x;
    const int head = blockIdx.y;
    const int tid = threadIdx.x;
    const int warp = tid >> 5, lane = tid & 31;
    const int cnt = (cq == 32) ? 1 : 65;
    const int total = cq + cnt;

    for (int idx = tid; idx < total * 16; idx += 256) {
        int kk = idx >> 4, seg = idx & 15;
        int kp = (kk < cq) ? kk * 65 : cq * 65 + (kk - cq);
        const float* base = qkv + (size_t)kp * 3072 + head * 64 + seg * 4;
        float4 kv = *(const float4*)(base + 1024);
        float4 vv = *(const float4*)(base + 2048);
        *(float4*)&sK[kk * KPAD + seg * 4] = kv;
        *(float4*)&sV[kk * KPAD + seg * 4] = vv;
    }
    __syncthreads();

    for (int j = warp; j < cnt; j += 8) {
        const int p = cq * 65 + j;
        const int nk = cq + j + 1;

        float2 q2 = *(const float2*)(qkv + (size_t)p * 3072 + head * 64 + 2 * lane);
        sq[warp * 64 + 2 * lane]     = q2.x;
        sq[warp * 64 + 2 * lane + 1] = q2.y;
        __syncwarp();

        float mx = -1e30f;
        for (int kb2 = 0; kb2 < nk; kb2 += 32) {
            int kk = kb2 + lane;
            float s = -1e30f;
            if (kk < nk) {
                float a = 0.f;
#pragma unroll
                for (int d4 = 0; d4 < 16; d4++) {
                    float4 qv = *(const float4*)&sq[warp * 64 + d4 * 4];
                    float4 kv = *(const float4*)&sK[kk * KPAD + d4 * 4];
                    a += qv.x * kv.x + qv.y * kv.y + qv.z * kv.z + qv.w * kv.w;
                }
                s = a * 0.125f;
                sp[warp * 100 + kk] = s;
            }
            mx = fmaxf(mx, s);
        }
        mx = fmaxf(mx, __shfl_xor_sync(0xffffffffu, mx, 16));
        mx = fmaxf(mx, __shfl_xor_sync(0xffffffffu, mx, 8));
        mx = fmaxf(mx, __shfl_xor_sync(0xffffffffu, mx, 4));
        mx = fmaxf(mx, __shfl_xor_sync(0xffffffffu, mx, 2));
        mx = fmaxf(mx, __shfl_xor_sync(0xffffffffu, mx, 1));
        __syncwarp();

        float sum = 0.f;
        for (int kk = lane; kk < nk; kk += 32) {
            float e = __expf(sp[warp * 100 + kk] - mx);
            sp[warp * 100 + kk] = e;
            sum += e;
        }
        sum += __shfl_xor_sync(0xffffffffu, sum, 16);
        sum += __shfl_xor_sync(0xffffffffu, sum, 8);
        sum += __shfl_xor_sync(0xffffffffu, sum, 4);
        sum += __shfl_xor_sync(0xffffffffu, sum, 2);
        sum += __shfl_xor_sync(0xffffffffu, sum, 1);
        __syncwarp();
        float inv = 1.f / sum;

        float2 acc = make_float2(0.f, 0.f);
        for (int kk = 0; kk < nk; kk++) {
            float pr = sp[warp * 100 + kk];
            float2 v2 = *(const float2*)&sV[kk * KPAD + 2 * lane];
            acc.x += pr * v2.x;
            acc.y += pr * v2.y;
        }
        st_bf16pair(yhi, ylo, (size_t)p * CATD + head * 64 + 2 * lane,
                    acc.x * inv, acc.y * inv);
        __syncwarp();
    }
}

// ---------------------------------------------------------------------------
extern "C" void kernel_launch(void* const* d_in, const int* in_sizes, int n_in,
                              void* d_out, int out_size)
{
    const float* x        = (const float*)d_in[0];
    const float* W_expand = (const float*)d_in[1];
    const float* W_comp   = (const float*)d_in[2];
    const float* b_comp   = (const float*)d_in[3];
    const float* dummy_fx = (const float*)d_in[4];
    const float* W_qkv    = (const float*)d_in[5];
    const float* W_o      = (const float*)d_in[6];
    const float* W_final  = (const float*)d_in[7];
    const float* cosb     = (const float*)d_in[8];
    const float* sinb     = (const float*)d_in[9];
    float* out = (float*)d_out;

    float *fxpart, *qkv;
    bf16 *xhi, *xlo, *hhi, *hlo, *yhi, *ylo, *y2hi, *y2lo;
    bf16 *wexphi, *wexplo, *wqkvhi, *wqkvlo, *wohi, *wolo, *wfinhi, *wfinlo;
    cudaGetSymbolAddress((void**)&fxpart, g_fxpart);
    cudaGetSymbolAddress((void**)&qkv,    g_qkv);
    cudaGetSymbolAddress((void**)&xhi,    g_xhi);
    cudaGetSymbolAddress((void**)&xlo,    g_xlo);
    cudaGetSymbolAddress((void**)&hhi,    g_hhi);
    cudaGetSymbolAddress((void**)&hlo,    g_hlo);
    cudaGetSymbolAddress((void**)&yhi,    g_yhi);
    cudaGetSymbolAddress((void**)&ylo,    g_ylo);
    cudaGetSymbolAddress((void**)&y2hi,   g_y2hi);
    cudaGetSymbolAddress((void**)&y2lo,   g_y2lo);
    cudaGetSymbolAddress((void**)&wexphi, g_wexphi);
    cudaGetSymbolAddress((void**)&wexplo, g_wexplo);
    cudaGetSymbolAddress((void**)&wqkvhi, g_wqkvhi);
    cudaGetSymbolAddress((void**)&wqkvlo, g_wqkvlo);
    cudaGetSymbolAddress((void**)&wohi,   g_wohi);
    cudaGetSymbolAddress((void**)&wolo,   g_wolo);
    cudaGetSymbolAddress((void**)&wfinhi, g_wfinhi);
    cudaGetSymbolAddress((void**)&wfinlo, g_wfinlo);

    cudaFuncSetAttribute(mma_gemm<0, 1>, cudaFuncAttributeMaxDynamicSharedMemorySize, DSMEM);
    cudaFuncSetAttribute(mma_gemm<0, 3>, cudaFuncAttributeMaxDynamicSharedMemorySize, DSMEM);
    cudaFuncSetAttribute(mma_gemm<0, 2>, cudaFuncAttributeMaxDynamicSharedMemorySize, DSMEM);
    cudaFuncSetAttribute(mma_gemm<1, 0>, cudaFuncAttributeMaxDynamicSharedMemorySize, DSMEM);
    cudaFuncSetAttribute(attn_kernel,    cudaFuncAttributeMaxDynamicSharedMemorySize, ATTN_SMEM);

    // 0. convert x + weights to bf16 hi/lo
    cvt_kernel<<<2048, 256>>>(x,        xhi,    xlo,    524288);
    cvt_kernel<<<1024, 256>>>(W_expand, wexphi, wexplo, 262144);
    cvt_kernel<<<3072, 256>>>(W_qkv,    wqkvhi, wqkvlo, 786432);
    cvt_kernel<<<1024, 256>>>(W_o,      wohi,   wolo,   262144);
    cvt_kernel<<<1024, 256>>>(W_final,  wfinhi, wfinlo, 262144);

    // 1. fx partials (tensor-core split-K)
    comp_kernel<<<dim3(8, CSLICES), 256>>>(xhi, xlo, W_comp, fxpart);

    // 2. reduce partials -> bf16 anchor rows of h
    fx_reduce<<<dim3(8, 33), 128>>>(fxpart, dummy_fx, b_comp, hhi, hlo);

    // 3. xe = x @ W_expand -> scattered bf16 rows of h
    mma_gemm<0, 1><<<dim3(8, 16), 256, DSMEM>>>(xhi, xlo, wexphi, wexplo,
                                                nullptr, hhi, hlo, nullptr, nullptr,
                                                2048, 1024, 1024);

    // 4. qkv = h @ W_qkv (fp32 out, RoPE fused into epilogue for q/k)
    mma_gemm<0, 3><<<dim3(24, 17), 256, DSMEM>>>(hhi, hlo, wqkvhi, wqkvlo,
                                                 qkv, nullptr, nullptr, cosb, sinb,
                                                 S_LEN, 3072, 1024);

    // 5. sparse CAT attention -> bf16 y
    attn_kernel<<<dim3(33, 16), 256, ATTN_SMEM>>>(qkv, yhi, ylo);

    // 6. y2 = y @ W_o (bf16 out)
    mma_gemm<0, 2><<<dim3(8, 17), 256, DSMEM>>>(yhi, ylo, wohi, wolo,
                                                nullptr, y2hi, y2lo, nullptr, nullptr,
                                                S_LEN, 1024, 1024);

    // 7. out = gather(y2) @ W_final (fp32 out)
    mma_gemm<1, 0><<<dim3(8, 16), 256, DSMEM>>>(y2hi, y2lo, wfinhi, wfinlo,
                                                out, nullptr, nullptr, nullptr, nullptr,
                                                2048, 1024, 1024);
}